// round 4
// baseline (speedup 1.0000x reference)
#include <cuda_runtime.h>
#include <cuda_bf16.h>
#include <math.h>
#include <stdint.h>

#define TOK    16384
#define DMODEL 1024
#define DFF    2048
#define TSEQ   512
#define TDSZ   (TSEQ*DMODEL)

// ------------------------- scratch (device globals; no allocs) -------------
__device__ float g_ln  [TOK*DMODEL];
__device__ float g_q   [TOK*DMODEL];
__device__ float g_k   [TOK*DMODEL];
__device__ float g_v   [TOK*DMODEL];
__device__ float g_y   [TOK*DMODEL];
__device__ float g_y2  [TOK*DMODEL];
__device__ float g_dy  [TOK*DMODEL];
__device__ float g_wide[TOK*DFF];
__device__ float g_MT   [DMODEL*DMODEL];
__device__ float g_MinvT[DMODEL*DMODEL];
__device__ float g_W1f  [DMODEL*DFF];
__device__ float g_W2f  [DFF*DMODEL];
__device__ float g_b2f  [DMODEL];
__device__ float g_Bc1  [3*DMODEL*DMODEL];
__device__ float g_Bc2  [3*DMODEL*DMODEL];

// ------------------------- helpers ----------------------------------------
__device__ __forceinline__ uint32_t f2tf(float f){
  uint32_t r; asm("cvt.rna.tf32.f32 %0, %1;" : "=r"(r) : "f"(f)); return r;
}
__device__ __forceinline__ void mma8(float* d, const uint32_t* a, const uint32_t* b){
  asm volatile(
    "mma.sync.aligned.m16n8k8.row.col.f32.tf32.tf32.f32 "
    "{%0,%1,%2,%3}, {%4,%5,%6,%7}, {%8,%9}, {%0,%1,%2,%3};"
    : "+f"(d[0]), "+f"(d[1]), "+f"(d[2]), "+f"(d[3])
    : "r"(a[0]), "r"(a[1]), "r"(a[2]), "r"(a[3]), "r"(b[0]), "r"(b[1]));
}
__device__ __forceinline__ void cp16(float* sdst, const float* gsrc, bool pred){
  uint32_t s = (uint32_t)__cvta_generic_to_shared(sdst);
  int n = pred ? 16 : 0;
  asm volatile("cp.async.cg.shared.global [%0], [%1], 16, %2;" :: "r"(s), "l"(gsrc), "r"(n));
}
__device__ __forceinline__ void cp_commit(){ asm volatile("cp.async.commit_group;"); }
template<int N> __device__ __forceinline__ void cp_wait(){
  asm volatile("cp.async.wait_group %0;" :: "n"(N));
}
__device__ __forceinline__ float gelu_f(float x){
  return 0.5f*x*(1.f + erff(x*0.70710678118654752f));
}
__device__ __forceinline__ float silu_f(float x){ return x/(1.f+expf(-x)); }

// ------------------------- DCT matrices ------------------------------------
__global__ void build_dct_kernel(){
  int idx = blockIdx.x*256 + threadIdx.x;   // < 1024*1024
  int i = idx >> 10, j = idx & 1023;
  const float c = 3.14159265358979323846f/2048.f;
  int m1 = ((2*i+1)*j) & 4095;              // MT[n=i][k=j] = M[k][n]
  g_MT[idx] = 2.f*cosf((float)m1 * c);
  int m2 = ((2*j+1)*i) & 4095;              // MinvT[k=i][n=j] = Minv[n][k]
  float sc = (i==0) ? (0.5f/1024.f) : (1.f/1024.f);
  g_MinvT[idx] = cosf((float)m2 * c) * sc;
}

// conv w (O,I,3) -> Bc[r][i][o]
__global__ void pack_conv_kernel(const float* __restrict__ w, float* __restrict__ Bc){
  int idx = blockIdx.x*256 + threadIdx.x;   // < 3*1024*1024
  int o = idx & 1023;
  int i = (idx >> 10) & 1023;
  int r = idx >> 20;
  Bc[idx] = w[((o<<10) + i)*3 + r];
}

// b2f[n] = sum_k lin2_b[k] * MinvT[k][n]
__global__ void fold_bias_kernel(const float* __restrict__ b2){
  int n = blockIdx.x*256 + threadIdx.x;
  float s = 0.f;
  for (int k2 = 0; k2 < 1024; k2++) s += b2[k2]*g_MinvT[(k2<<10)+n];
  g_b2f[n] = s;
}

// ------------------------- LayerNorm over last dim (1024) ------------------
__global__ __launch_bounds__(256) void ln_kernel(
    const float* __restrict__ x, const float* __restrict__ gw,
    const float* __restrict__ gb, float* __restrict__ out)
{
  __shared__ float rs[8], rq[8], mv[2];
  const int row = blockIdx.x, tid = threadIdx.x;
  const int lane = tid & 31, warp = tid >> 5;
  const float4 xv = *(const float4*)(x + (size_t)row*1024 + tid*4);
  float s = xv.x+xv.y+xv.z+xv.w;
  float q = xv.x*xv.x+xv.y*xv.y+xv.z*xv.z+xv.w*xv.w;
  #pragma unroll
  for (int o=16;o;o>>=1){ s += __shfl_xor_sync(0xffffffffu,s,o); q += __shfl_xor_sync(0xffffffffu,q,o); }
  if (lane==0){ rs[warp]=s; rq[warp]=q; }
  __syncthreads();
  if (tid==0){
    float ss=0.f, qq=0.f;
    #pragma unroll
    for (int w2=0;w2<8;w2++){ ss+=rs[w2]; qq+=rq[w2]; }
    float m = ss*(1.f/1024.f);
    float var = qq*(1.f/1024.f) - m*m;
    mv[0]=m; mv[1]=rsqrtf(var + 1e-5f);
  }
  __syncthreads();
  const float m = mv[0], inv = mv[1];
  const float4 g4 = *(const float4*)(gw + tid*4);
  const float4 b4 = *(const float4*)(gb + tid*4);
  float4 o4;
  o4.x = (xv.x-m)*inv*g4.x + b4.x;
  o4.y = (xv.y-m)*inv*g4.y + b4.y;
  o4.z = (xv.z-m)*inv*g4.z + b4.z;
  o4.w = (xv.w-m)*inv*g4.w + b4.w;
  *(float4*)(out + (size_t)row*1024 + tid*4) = o4;
}

// ------------------------- tf32 GEMM ---------------------------------------
// C = act(A@B + bias) + R.  A: MxK (lda = K, or DMODEL in conv mode),
// B: KxN row-major.  conv mode: K = 3*1024; r = k/1024 selects time-shift
// (r-1) on A rows, masked at T=512 sequence boundaries.
#define BM 128
#define BN 128
#define BK 32
#define ASTR 36
#define BSTR 136
#define AELE (BM*ASTR)
#define BELE (BK*BSTR)
#define GEMM_SMEM ((2*AELE + 2*BELE)*4)

__device__ __forceinline__ void gemm_load_stage(
    const float* __restrict__ A, const float* __restrict__ Bw,
    float* asb, float* bsb, int tid, int bm, int bn, int N, int lda,
    int conv, int kt)
{
  const int k0 = kt*BK;
  int roff = 0, kk0 = k0;
  if (conv){ roff = (k0 >> 10) - 1; kk0 = k0 & 1023; }
  #pragma unroll
  for (int j=0;j<4;j++){
    int i = tid + j*256;
    int ar = i >> 3, ac = (i & 7)*4;
    int grow = bm + ar;
    bool pr = true; int srow = grow;
    if (conv){
      int tt = grow & (TSEQ-1);
      int tp = tt + roff;
      pr = (tp >= 0) && (tp < TSEQ);
      srow = pr ? (grow + roff) : grow;
    }
    cp16(asb + ar*ASTR + ac, A + (size_t)srow*lda + kk0 + ac, pr);
  }
  #pragma unroll
  for (int j=0;j<4;j++){
    int i = tid + j*256;
    int br = i >> 5, bc = (i & 31)*4;
    cp16(bsb + br*BSTR + bc, Bw + (size_t)(k0+br)*N + bn + bc, true);
  }
  cp_commit();
}

__global__ __launch_bounds__(256) void gemm_kernel(
    const float* __restrict__ A, const float* __restrict__ Bw,
    const float* __restrict__ bias, const float* __restrict__ Rres,
    float* __restrict__ C, int M, int N, int K, int act, int conv)
{
  extern __shared__ float sm[];
  float* As = sm;
  float* Bs = sm + 2*AELE;
  const int tid = threadIdx.x;
  const int bm = blockIdx.y*BM, bn = blockIdx.x*BN;
  const int lane = tid & 31, warp = tid >> 5;
  const int wm = warp >> 1, wn = warp & 1;
  const int rowW = wm*32, colW = wn*64;
  const int lda = conv ? DMODEL : K;
  const int KT = K / BK;

  float acc[2][8][4];
  #pragma unroll
  for (int a1=0;a1<2;a1++)
    #pragma unroll
    for (int a2=0;a2<8;a2++)
      #pragma unroll
      for (int a3=0;a3<4;a3++) acc[a1][a2][a3]=0.f;

  gemm_load_stage(A,Bw,As,Bs,tid,bm,bn,N,lda,conv,0);
  for (int kt=0; kt<KT; kt++){
    const int cur = kt & 1;
    if (kt+1 < KT){
      gemm_load_stage(A,Bw,As+(cur^1)*AELE,Bs+(cur^1)*BELE,tid,bm,bn,N,lda,conv,kt+1);
      cp_wait<1>();
    } else {
      cp_wait<0>();
    }
    __syncthreads();
    const float* asb = As + cur*AELE;
    const float* bsb = Bs + cur*BELE;
    #pragma unroll
    for (int ks=0; ks<4; ks++){
      const int k8 = ks*8;
      uint32_t af[2][4], bf[8][2];
      #pragma unroll
      for (int mt=0; mt<2; mt++){
        const int r = rowW + mt*16 + (lane>>2);
        const int c = k8 + (lane&3);
        af[mt][0] = f2tf(asb[r*ASTR + c]);
        af[mt][1] = f2tf(asb[(r+8)*ASTR + c]);
        af[mt][2] = f2tf(asb[r*ASTR + c + 4]);
        af[mt][3] = f2tf(asb[(r+8)*ASTR + c + 4]);
      }
      #pragma unroll
      for (int nt=0; nt<8; nt++){
        const int cc = colW + nt*8 + (lane>>2);
        bf[nt][0] = f2tf(bsb[(k8 + (lane&3))*BSTR + cc]);
        bf[nt][1] = f2tf(bsb[(k8 + 4 + (lane&3))*BSTR + cc]);
      }
      #pragma unroll
      for (int mt=0; mt<2; mt++)
        #pragma unroll
        for (int nt=0; nt<8; nt++)
          mma8(acc[mt][nt], af[mt], bf[nt]);
    }
    __syncthreads();
  }

  #pragma unroll
  for (int mt=0; mt<2; mt++){
    const int r0 = bm + rowW + mt*16 + (lane>>2);
    #pragma unroll
    for (int nt=0; nt<8; nt++){
      const int c0 = bn + colW + nt*8 + (lane&3)*2;
      const float bb0 = bias ? bias[c0]   : 0.f;
      const float bb1 = bias ? bias[c0+1] : 0.f;
      #pragma unroll
      for (int rr=0; rr<2; rr++){
        const int r = r0 + rr*8;
        float v0 = acc[mt][nt][rr*2+0] + bb0;
        float v1 = acc[mt][nt][rr*2+1] + bb1;
        if (act==1){ v0 = gelu_f(v0); v1 = gelu_f(v1); }
        else if (act==2){ v0 = silu_f(v0); v1 = silu_f(v1); }
        if (Rres){
          const float* rp = Rres + (size_t)r*N + c0;
          v0 += rp[0]; v1 += rp[1];
        }
        *(float2*)(C + (size_t)r*N + c0) = make_float2(v0, v1);
      }
    }
  }
}

// ------------------------- channel attention -------------------------------
// Per (b,h): Q,K,V are contiguous 64x512 row-major (the reshape is a flat
// view); S = Q K^T * temp[h]; softmax rows; out = S @ V; y = out + x.
__global__ __launch_bounds__(256) void attn_kernel(
    const float* __restrict__ q, const float* __restrict__ k,
    const float* __restrict__ v, const float* __restrict__ temp,
    const float* __restrict__ x, float* __restrict__ y)
{
  __shared__ float Qs[64*36];
  __shared__ float Ks[64*36];
  __shared__ float Ps[64*65];
  const int bh = blockIdx.x;
  const int b = bh >> 4, h = bh & 15;
  const size_t base = (size_t)b*TDSZ + (size_t)h*(64*TSEQ);
  const float* Q  = q + base;
  const float* Kp = k + base;
  const float* V  = v + base;
  const int tid = threadIdx.x;
  const int tx = tid & 15, ty = tid >> 4;
  const int r0 = ty*4, c0 = tx*4;

  float acc[16];
  #pragma unroll
  for (int i2=0;i2<16;i2++) acc[i2]=0.f;

  for (int t0 = 0; t0 < TSEQ; t0 += 32){
    #pragma unroll
    for (int j=0;j<2;j++){
      int i = tid + j*256;
      int row = i >> 3, col = (i & 7)*4;
      *(float4*)(Qs + row*36 + col) = *(const float4*)(Q  + row*TSEQ + t0 + col);
      *(float4*)(Ks + row*36 + col) = *(const float4*)(Kp + row*TSEQ + t0 + col);
    }
    __syncthreads();
    for (int kk=0; kk<32; kk++){
      float qv[4], kv[4];
      #pragma unroll
      for (int i=0;i<4;i++) qv[i] = Qs[(r0+i)*36 + kk];
      #pragma unroll
      for (int j=0;j<4;j++) kv[j] = Ks[(c0+j)*36 + kk];
      #pragma unroll
      for (int i=0;i<4;i++)
        #pragma unroll
        for (int j=0;j<4;j++) acc[i*4+j] += qv[i]*kv[j];
    }
    __syncthreads();
  }
  const float tmp = temp[h];
  #pragma unroll
  for (int i=0;i<4;i++)
    #pragma unroll
    for (int j=0;j<4;j++) Ps[(r0+i)*65 + c0 + j] = acc[i*4+j]*tmp;
  __syncthreads();

  if (tid < 64){
    float* row = Ps + tid*65;
    float m = row[0];
    for (int e=1;e<64;e++) m = fmaxf(m, row[e]);
    float s = 0.f;
    for (int e=0;e<64;e++){ float ev = expf(row[e]-m); row[e]=ev; s+=ev; }
    float inv = 1.f/s;
    for (int e=0;e<64;e++) row[e] *= inv;
  }
  __syncthreads();

  // out = P @ V, add x; Vs reuses Qs.
  const int tc = tx*2;
  for (int t0 = 0; t0 < TSEQ; t0 += 32){
    #pragma unroll
    for (int j=0;j<2;j++){
      int i = tid + j*256;
      int row = i >> 3, col = (i & 7)*4;
      *(float4*)(Qs + row*36 + col) = *(const float4*)(V + row*TSEQ + t0 + col);
    }
    __syncthreads();
    float a2[4][2];
    #pragma unroll
    for (int i=0;i<4;i++){ a2[i][0]=0.f; a2[i][1]=0.f; }
    for (int e=0;e<64;e++){
      float v0 = Qs[e*36 + tc], v1 = Qs[e*36 + tc + 1];
      #pragma unroll
      for (int i=0;i<4;i++){
        float p = Ps[(r0+i)*65 + e];
        a2[i][0] += p*v0; a2[i][1] += p*v1;
      }
    }
    #pragma unroll
    for (int i=0;i<4;i++){
      size_t o = base + (size_t)(r0+i)*TSEQ + t0 + tc;
      y[o]   = a2[i][0] + x[o];
      y[o+1] = a2[i][1] + x[o+1];
    }
    __syncthreads();
  }
}

// ------------------------- launch ------------------------------------------
static void launch_gemm(const float* A, const float* B, const float* bias,
                        const float* R, float* C, int M, int N, int K,
                        int act, int conv){
  dim3 grid(N/BN, M/BM);
  gemm_kernel<<<grid, 256, GEMM_SMEM>>>(A, B, bias, R, C, M, N, K, act, conv);
}

extern "C" void kernel_launch(void* const* d_in, const int* in_sizes, int n_in,
                              void* d_out, int out_size) {
  const float* x       = (const float*)d_in[0];
  const float* q_w     = (const float*)d_in[1];
  const float* q_b     = (const float*)d_in[2];
  const float* k_w     = (const float*)d_in[3];
  const float* k_b     = (const float*)d_in[4];
  const float* v_w     = (const float*)d_in[5];
  const float* v_b     = (const float*)d_in[6];
  const float* temp    = (const float*)d_in[7];
  const float* ln1_w   = (const float*)d_in[8];
  const float* ln1_b   = (const float*)d_in[9];
  const float* ln2_w   = (const float*)d_in[10];
  const float* ln2_b   = (const float*)d_in[11];
  const float* ln3_w   = (const float*)d_in[12];
  const float* ln3_b   = (const float*)d_in[13];
  const float* ln4_w   = (const float*)d_in[14];
  const float* ln4_b   = (const float*)d_in[15];
  const float* lin1_w  = (const float*)d_in[16];
  const float* lin1_b  = (const float*)d_in[17];
  const float* lin2_w  = (const float*)d_in[18];
  const float* lin2_b  = (const float*)d_in[19];
  const float* mlp1_w1 = (const float*)d_in[20];
  const float* mlp1_b1 = (const float*)d_in[21];
  const float* mlp1_w2 = (const float*)d_in[22];
  const float* mlp1_b2 = (const float*)d_in[23];
  const float* mlp2_w1 = (const float*)d_in[24];
  const float* mlp2_b1 = (const float*)d_in[25];
  const float* mlp2_w2 = (const float*)d_in[26];
  const float* mlp2_b2 = (const float*)d_in[27];
  const float* conv1_w = (const float*)d_in[28];
  const float* conv1_b = (const float*)d_in[29];
  const float* conv2_w = (const float*)d_in[30];
  const float* conv2_b = (const float*)d_in[31];
  float* out = (float*)d_out;

  cudaFuncSetAttribute(gemm_kernel, cudaFuncAttributeMaxDynamicSharedMemorySize, GEMM_SMEM);

  float *p_ln, *p_q, *p_k, *p_v, *p_y, *p_y2, *p_dy, *p_wide;
  float *p_MT, *p_MinvT, *p_W1f, *p_W2f, *p_b2f, *p_Bc1, *p_Bc2;
  cudaGetSymbolAddress((void**)&p_ln,   g_ln);
  cudaGetSymbolAddress((void**)&p_q,    g_q);
  cudaGetSymbolAddress((void**)&p_k,    g_k);
  cudaGetSymbolAddress((void**)&p_v,    g_v);
  cudaGetSymbolAddress((void**)&p_y,    g_y);
  cudaGetSymbolAddress((void**)&p_y2,   g_y2);
  cudaGetSymbolAddress((void**)&p_dy,   g_dy);
  cudaGetSymbolAddress((void**)&p_wide, g_wide);
  cudaGetSymbolAddress((void**)&p_MT,   g_MT);
  cudaGetSymbolAddress((void**)&p_MinvT,g_MinvT);
  cudaGetSymbolAddress((void**)&p_W1f,  g_W1f);
  cudaGetSymbolAddress((void**)&p_W2f,  g_W2f);
  cudaGetSymbolAddress((void**)&p_b2f,  g_b2f);
  cudaGetSymbolAddress((void**)&p_Bc1,  g_Bc1);
  cudaGetSymbolAddress((void**)&p_Bc2,  g_Bc2);

  // one-time (per launch) prep
  build_dct_kernel<<<4096, 256>>>();
  pack_conv_kernel<<<12288, 256>>>(conv1_w, p_Bc1);
  pack_conv_kernel<<<12288, 256>>>(conv2_w, p_Bc2);
  fold_bias_kernel<<<4, 256>>>(lin2_b);
  launch_gemm(p_MT,   lin1_w,  nullptr, nullptr, p_W1f, DMODEL, DFF,    DMODEL, 0, 0);
  launch_gemm(lin2_w, p_MinvT, nullptr, nullptr, p_W2f, DFF,    DMODEL, DMODEL, 0, 0);

  // attention block
  ln_kernel<<<TOK, 256>>>(x, ln1_w, ln1_b, p_ln);
  launch_gemm(p_ln, q_w, q_b, nullptr, p_q, TOK, DMODEL, DMODEL, 0, 0);
  launch_gemm(p_ln, k_w, k_b, nullptr, p_k, TOK, DMODEL, DMODEL, 0, 0);
  launch_gemm(p_ln, v_w, v_b, nullptr, p_v, TOK, DMODEL, DMODEL, 0, 0);
  attn_kernel<<<512, 256>>>(p_q, p_k, p_v, temp, x, p_y);

  // DCT-folded MLP
  ln_kernel<<<TOK, 256>>>(p_y, ln2_w, ln2_b, p_ln);
  launch_gemm(p_ln,   p_W1f, lin1_b, nullptr, p_wide, TOK, DFF,    DMODEL, 1, 0);
  launch_gemm(p_wide, p_W2f, p_b2f,  nullptr, p_dy,   TOK, DMODEL, DFF,    0, 0);

  // mlp1(d_y) + y
  launch_gemm(p_dy,   mlp1_w1, mlp1_b1, nullptr, p_wide, TOK, DFF,    DMODEL, 1, 0);
  launch_gemm(p_wide, mlp1_w2, mlp1_b2, p_y,     p_y2,   TOK, DMODEL, DFF,    0, 0);

  // mlp2(ln3(y)) added
  ln_kernel<<<TOK, 256>>>(p_y, ln3_w, ln3_b, p_ln);
  launch_gemm(p_ln,   mlp2_w1, mlp2_b1, nullptr, p_wide, TOK, DFF,    DMODEL, 1, 0);
  launch_gemm(p_wide, mlp2_w2, mlp2_b2, p_y2,    p_y2,   TOK, DMODEL, DFF,    0, 0);

  // conv path (as shifted GEMMs, K=3072), silu between; final residual y2
  ln_kernel<<<TOK, 256>>>(p_y2, ln4_w, ln4_b, p_ln);
  launch_gemm(p_ln, p_Bc1, conv1_b, nullptr, p_q, TOK, DMODEL, 3*DMODEL, 2, 1);
  launch_gemm(p_q,  p_Bc2, conv2_b, p_y2,    out, TOK, DMODEL, 3*DMODEL, 0, 1);
}

// round 5
// speedup vs baseline: 1.0264x; 1.0264x over previous
#include <cuda_runtime.h>
#include <cuda_bf16.h>
#include <math.h>
#include <stdint.h>

#define TOK    16384
#define DMODEL 1024
#define DFF    2048
#define TSEQ   512
#define TDSZ   (TSEQ*DMODEL)

// ------------------------- scratch (device globals; no allocs) -------------
__device__ float g_ln  [TOK*DMODEL];
__device__ float g_q   [TOK*DMODEL];
__device__ float g_k   [TOK*DMODEL];
__device__ float g_v   [TOK*DMODEL];
__device__ float g_y   [TOK*DMODEL];
__device__ float g_y2  [TOK*DMODEL];
__device__ float g_dy  [TOK*DMODEL];
__device__ float g_wide[TOK*DFF];
__device__ float g_MT   [DMODEL*DMODEL];   // MT[n][k] = M[k][n], tf32-rounded
__device__ float g_MinvA[DMODEL*DMODEL];   // Minv[n][k], tf32-rounded
__device__ float g_W1fT [DFF*DMODEL];      // Bt for lin1 gemm: [2048][1024]
__device__ float g_W2fT [DMODEL*DFF];      // Bt for lin2 gemm: [1024][2048]
__device__ float g_b2f  [DMODEL];
__device__ float g_Bc1t [DMODEL*3*DMODEL]; // [o][r*1024+i]
__device__ float g_Bc2t [DMODEL*3*DMODEL];
__device__ float g_qwt  [DMODEL*DMODEL];   // q_w^T rounded
__device__ float g_kwt  [DMODEL*DMODEL];
__device__ float g_vwt  [DMODEL*DMODEL];
__device__ float g_lin1t[DFF*DMODEL];      // lin1_w^T rounded
__device__ float g_lin2r[DFF*DMODEL];      // lin2_w rounded (no transpose)
__device__ float g_m11t [DFF*DMODEL];      // mlp1_w1^T
__device__ float g_m12t [DMODEL*DFF];      // mlp1_w2^T
__device__ float g_m21t [DFF*DMODEL];      // mlp2_w1^T
__device__ float g_m22t [DMODEL*DFF];      // mlp2_w2^T

// ------------------------- helpers ----------------------------------------
__device__ __forceinline__ uint32_t f2tf(float f){
  uint32_t r; asm("cvt.rna.tf32.f32 %0, %1;" : "=r"(r) : "f"(f)); return r;
}
__device__ __forceinline__ float tf32r(float f){
  return __uint_as_float(f2tf(f));
}
__device__ __forceinline__ void mma8(float* d, const uint32_t* a, const uint32_t* b){
  asm volatile(
    "mma.sync.aligned.m16n8k8.row.col.f32.tf32.tf32.f32 "
    "{%0,%1,%2,%3}, {%4,%5,%6,%7}, {%8,%9}, {%0,%1,%2,%3};"
    : "+f"(d[0]), "+f"(d[1]), "+f"(d[2]), "+f"(d[3])
    : "r"(a[0]), "r"(a[1]), "r"(a[2]), "r"(a[3]), "r"(b[0]), "r"(b[1]));
}
__device__ __forceinline__ void cp16(float* sdst, const float* gsrc, bool pred){
  uint32_t s = (uint32_t)__cvta_generic_to_shared(sdst);
  int n = pred ? 16 : 0;
  asm volatile("cp.async.cg.shared.global [%0], [%1], 16, %2;" :: "r"(s), "l"(gsrc), "r"(n));
}
__device__ __forceinline__ void cp_commit(){ asm volatile("cp.async.commit_group;"); }
template<int N> __device__ __forceinline__ void cp_wait(){
  asm volatile("cp.async.wait_group %0;" :: "n"(N));
}
__device__ __forceinline__ float gelu_f(float x){
  return 0.5f*x*(1.f + erff(x*0.70710678118654752f));
}
__device__ __forceinline__ float silu_f(float x){ return x/(1.f+expf(-x)); }

// ------------------------- prep kernels ------------------------------------
__global__ void build_dct_kernel(){
  int idx = blockIdx.x*256 + threadIdx.x;   // < 1024*1024
  int i = idx >> 10, j = idx & 1023;        // i = n, j = k
  const float c = 3.14159265358979323846f/2048.f;
  int m1 = ((2*i+1)*j) & 4095;
  g_MT[idx] = tf32r(2.f*cosf((float)m1 * c));          // MT[n][k]
  float sc = (j==0) ? (0.5f/1024.f) : (1.f/1024.f);
  g_MinvA[idx] = tf32r(cosf((float)m1 * c) * sc);      // Minv[n][k]
}

// conv w (O,I,3) -> Bt[o][r*1024+i], rounded
__global__ void pack_conv_kernel(const float* __restrict__ w, float* __restrict__ Bt){
  int idx = blockIdx.x*256 + threadIdx.x;   // < 3*1024*1024  (out-linear)
  int o = idx >> 12 >> 0;  // idx / 3072? no: use explicit
  o = idx / 3072;
  int rem = idx - o*3072;
  int r = rem >> 10;
  int i = rem & 1023;
  Bt[idx] = tf32r(w[((o<<10) + i)*3 + r]);
}

// tiled transpose + round: src[R][C] -> dst[C][R]
__global__ void tcopy_kernel(const float* __restrict__ src, float* __restrict__ dst,
                             int R, int C){
  __shared__ float t[32][33];
  int bx = blockIdx.x*32, by = blockIdx.y*32;
  int x = threadIdx.x, y = threadIdx.y;     // block (32,8)
  #pragma unroll
  for (int j=0;j<32;j+=8)
    t[y+j][x] = src[(size_t)(by+y+j)*C + bx + x];
  __syncthreads();
  #pragma unroll
  for (int j=0;j<32;j+=8)
    dst[(size_t)(bx+y+j)*R + by + x] = tf32r(t[x][y+j]);
}

// elementwise rounded copy
__global__ void rcopy_kernel(const float* __restrict__ src, float* __restrict__ dst){
  int idx = blockIdx.x*256 + threadIdx.x;
  float4 v = *(const float4*)(src + idx*4);
  v.x = tf32r(v.x); v.y = tf32r(v.y); v.z = tf32r(v.z); v.w = tf32r(v.w);
  *(float4*)(dst + idx*4) = v;
}

// b2f[n] = sum_k lin2_b[k] * Minv[n][k]
__global__ __launch_bounds__(256) void fold_bias_kernel(const float* __restrict__ b2){
  __shared__ float red[8];
  const int n = blockIdx.x, tid = threadIdx.x;
  const int lane = tid & 31, warp = tid >> 5;
  float s = 0.f;
  for (int k = tid; k < 1024; k += 256) s += b2[k]*g_MinvA[(n<<10)+k];
  #pragma unroll
  for (int o=16;o;o>>=1) s += __shfl_xor_sync(0xffffffffu,s,o);
  if (lane==0) red[warp]=s;
  __syncthreads();
  if (tid==0){
    float t=0.f;
    #pragma unroll
    for (int w2=0;w2<8;w2++) t+=red[w2];
    g_b2f[n]=t;
  }
}

// ------------------------- LayerNorm over last dim (1024), tf32-rounded out
__global__ __launch_bounds__(256) void ln_kernel(
    const float* __restrict__ x, const float* __restrict__ gw,
    const float* __restrict__ gb, float* __restrict__ out)
{
  __shared__ float rs[8], rq[8], mv[2];
  const int row = blockIdx.x, tid = threadIdx.x;
  const int lane = tid & 31, warp = tid >> 5;
  const float4 xv = *(const float4*)(x + (size_t)row*1024 + tid*4);
  float s = xv.x+xv.y+xv.z+xv.w;
  float q = xv.x*xv.x+xv.y*xv.y+xv.z*xv.z+xv.w*xv.w;
  #pragma unroll
  for (int o=16;o;o>>=1){ s += __shfl_xor_sync(0xffffffffu,s,o); q += __shfl_xor_sync(0xffffffffu,q,o); }
  if (lane==0){ rs[warp]=s; rq[warp]=q; }
  __syncthreads();
  if (tid==0){
    float ss=0.f, qq=0.f;
    #pragma unroll
    for (int w2=0;w2<8;w2++){ ss+=rs[w2]; qq+=rq[w2]; }
    float m = ss*(1.f/1024.f);
    float var = qq*(1.f/1024.f) - m*m;
    mv[0]=m; mv[1]=rsqrtf(var + 1e-5f);
  }
  __syncthreads();
  const float m = mv[0], inv = mv[1];
  const float4 g4 = *(const float4*)(gw + tid*4);
  const float4 b4 = *(const float4*)(gb + tid*4);
  float4 o4;
  o4.x = tf32r((xv.x-m)*inv*g4.x + b4.x);
  o4.y = tf32r((xv.y-m)*inv*g4.y + b4.y);
  o4.z = tf32r((xv.z-m)*inv*g4.z + b4.z);
  o4.w = tf32r((xv.w-m)*inv*g4.w + b4.w);
  *(float4*)(out + (size_t)row*1024 + tid*4) = o4;
}

// ------------------------- tf32 GEMM ---------------------------------------
// C = act(A@Bt^T + bias) [+ R] [tf32-round].  A: MxK row-major (lda=K, or
// DMODEL in conv mode), Bt: NxK row-major (ldb=K).  All operands pre-rounded
// to tf32.  conv mode: K=3*1024; r=k>>10 selects time-shift (r-1) on A rows,
// masked at T=512 sequence boundaries.  k slots inside each mma k8-block are
// permuted (slot q -> col 2q, slot q+4 -> col 2q+1) identically on A and B
// so fragments load as float2.
#define BM 128
#define BN 128
#define BK 32
#define ASTR 40
#define BTSTR 40
#define AELE (BM*ASTR)
#define BELE (BN*BTSTR)
#define GEMM_SMEM ((2*AELE + 2*BELE)*4)

__device__ __forceinline__ void gemm_load_stage(
    const float* __restrict__ A, const float* __restrict__ Bt,
    float* asb, float* bsb, int tid, int bm, int bn, int K, int lda,
    int conv, int kt)
{
  const int k0 = kt*BK;
  int roff = 0, kk0 = k0;
  if (conv){ roff = (k0 >> 10) - 1; kk0 = k0 & 1023; }
  #pragma unroll
  for (int j=0;j<4;j++){
    int i = tid + j*256;
    int ar = i >> 3, ac = (i & 7)*4;
    int grow = bm + ar;
    bool pr = true; int srow = grow;
    if (conv){
      int tt = grow & (TSEQ-1);
      int tp = tt + roff;
      pr = (tp >= 0) && (tp < TSEQ);
      srow = pr ? (grow + roff) : grow;
    }
    cp16(asb + ar*ASTR + ac, A + (size_t)srow*lda + kk0 + ac, pr);
  }
  #pragma unroll
  for (int j=0;j<4;j++){
    int i = tid + j*256;
    int br = i >> 3, bc = (i & 7)*4;
    cp16(bsb + br*BTSTR + bc, Bt + (size_t)(bn+br)*K + k0 + bc, true);
  }
  cp_commit();
}

__global__ __launch_bounds__(256) void gemm_kernel(
    const float* __restrict__ A, const float* __restrict__ Bt,
    const float* __restrict__ bias, const float* __restrict__ Rres,
    float* __restrict__ C, int M, int N, int K, int act, int conv, int rnd)
{
  extern __shared__ float sm[];
  float* As = sm;
  float* Bs = sm + 2*AELE;
  const int tid = threadIdx.x;
  const int bm = blockIdx.y*BM, bn = blockIdx.x*BN;
  const int lane = tid & 31, warp = tid >> 5;
  const int wm = warp >> 1, wn = warp & 1;
  const int rowW = wm*32, colW = wn*64;
  const int lda = conv ? DMODEL : K;
  const int KT = K / BK;
  const int q2 = (lane & 3)*2;
  const int aoff = (rowW + (lane>>2))*ASTR + q2;
  const int boff = (colW + (lane>>2))*BTSTR + q2;

  float acc[2][8][4];
  #pragma unroll
  for (int a1=0;a1<2;a1++)
    #pragma unroll
    for (int a2=0;a2<8;a2++)
      #pragma unroll
      for (int a3=0;a3<4;a3++) acc[a1][a2][a3]=0.f;

  gemm_load_stage(A,Bt,As,Bs,tid,bm,bn,K,lda,conv,0);
  for (int kt=0; kt<KT; kt++){
    const int cur = kt & 1;
    if (kt+1 < KT){
      gemm_load_stage(A,Bt,As+(cur^1)*AELE,Bs+(cur^1)*BELE,tid,bm,bn,K,lda,conv,kt+1);
      cp_wait<1>();
    } else {
      cp_wait<0>();
    }
    __syncthreads();
    const float* asb = As + cur*AELE;
    const float* bsb = Bs + cur*BELE;
    #pragma unroll
    for (int ks=0; ks<4; ks++){
      const int kb = ks*8;
      float2 fa[2][2]; float2 fb[8];
      #pragma unroll
      for (int mt=0; mt<2; mt++){
        fa[mt][0] = *(const float2*)(asb + aoff + mt*(16*ASTR) + kb);
        fa[mt][1] = *(const float2*)(asb + aoff + mt*(16*ASTR) + 8*ASTR + kb);
      }
      #pragma unroll
      for (int nt=0; nt<8; nt++)
        fb[nt] = *(const float2*)(bsb + boff + nt*(8*BTSTR) + kb);
      #pragma unroll
      for (int mt=0; mt<2; mt++){
        uint32_t a[4] = {__float_as_uint(fa[mt][0].x), __float_as_uint(fa[mt][1].x),
                         __float_as_uint(fa[mt][0].y), __float_as_uint(fa[mt][1].y)};
        #pragma unroll
        for (int nt=0; nt<8; nt++){
          uint32_t b[2] = {__float_as_uint(fb[nt].x), __float_as_uint(fb[nt].y)};
          mma8(acc[mt][nt], a, b);
        }
      }
    }
    __syncthreads();
  }

  #pragma unroll
  for (int mt=0; mt<2; mt++){
    const int r0 = bm + rowW + mt*16 + (lane>>2);
    #pragma unroll
    for (int nt=0; nt<8; nt++){
      const int c0 = bn + colW + nt*8 + (lane&3)*2;
      const float bb0 = bias ? bias[c0]   : 0.f;
      const float bb1 = bias ? bias[c0+1] : 0.f;
      #pragma unroll
      for (int rr=0; rr<2; rr++){
        const int r = r0 + rr*8;
        float v0 = acc[mt][nt][rr*2+0] + bb0;
        float v1 = acc[mt][nt][rr*2+1] + bb1;
        if (act==1){ v0 = gelu_f(v0); v1 = gelu_f(v1); }
        else if (act==2){ v0 = silu_f(v0); v1 = silu_f(v1); }
        if (Rres){
          const float* rp = Rres + (size_t)r*N + c0;
          v0 += rp[0]; v1 += rp[1];
        }
        if (rnd){ v0 = tf32r(v0); v1 = tf32r(v1); }
        *(float2*)(C + (size_t)r*N + c0) = make_float2(v0, v1);
      }
    }
  }
}

// ------------------------- channel attention -------------------------------
__global__ __launch_bounds__(256) void attn_kernel(
    const float* __restrict__ q, const float* __restrict__ k,
    const float* __restrict__ v, const float* __restrict__ temp,
    const float* __restrict__ x, float* __restrict__ y)
{
  __shared__ float Qs[64*36];
  __shared__ float Ks[64*36];
  __shared__ float Ps[64*65];
  const int bh = blockIdx.x;
  const int b = bh >> 4, h = bh & 15;
  const size_t base = (size_t)b*TDSZ + (size_t)h*(64*TSEQ);
  const float* Q  = q + base;
  const float* Kp = k + base;
  const float* V  = v + base;
  const int tid = threadIdx.x;
  const int tx = tid & 15, ty = tid >> 4;
  const int r0 = ty*4, c0 = tx*4;

  float acc[16];
  #pragma unroll
  for (int i2=0;i2<16;i2++) acc[i2]=0.f;

  for (int t0 = 0; t0 < TSEQ; t0 += 32){
    #pragma unroll
    for (int j=0;j<2;j++){
      int i = tid + j*256;
      int row = i >> 3, col = (i & 7)*4;
      *(float4*)(Qs + row*36 + col) = *(const float4*)(Q  + row*TSEQ + t0 + col);
      *(float4*)(Ks + row*36 + col) = *(const float4*)(Kp + row*TSEQ + t0 + col);
    }
    __syncthreads();
    for (int kk=0; kk<32; kk++){
      float qv[4], kv[4];
      #pragma unroll
      for (int i=0;i<4;i++) qv[i] = Qs[(r0+i)*36 + kk];
      #pragma unroll
      for (int j=0;j<4;j++) kv[j] = Ks[(c0+j)*36 + kk];
      #pragma unroll
      for (int i=0;i<4;i++)
        #pragma unroll
        for (int j=0;j<4;j++) acc[i*4+j] += qv[i]*kv[j];
    }
    __syncthreads();
  }
  const float tmp = temp[h];
  #pragma unroll
  for (int i=0;i<4;i++)
    #pragma unroll
    for (int j=0;j<4;j++) Ps[(r0+i)*65 + c0 + j] = acc[i*4+j]*tmp;
  __syncthreads();

  if (tid < 64){
    float* row = Ps + tid*65;
    float m = row[0];
    for (int e=1;e<64;e++) m = fmaxf(m, row[e]);
    float s = 0.f;
    for (int e=0;e<64;e++){ float ev = expf(row[e]-m); row[e]=ev; s+=ev; }
    float inv = 1.f/s;
    for (int e=0;e<64;e++) row[e] *= inv;
  }
  __syncthreads();

  const int tc = tx*2;
  for (int t0 = 0; t0 < TSEQ; t0 += 32){
    #pragma unroll
    for (int j=0;j<2;j++){
      int i = tid + j*256;
      int row = i >> 3, col = (i & 7)*4;
      *(float4*)(Qs + row*36 + col) = *(const float4*)(V + row*TSEQ + t0 + col);
    }
    __syncthreads();
    float a2[4][2];
    #pragma unroll
    for (int i=0;i<4;i++){ a2[i][0]=0.f; a2[i][1]=0.f; }
    for (int e=0;e<64;e++){
      float v0 = Qs[e*36 + tc], v1 = Qs[e*36 + tc + 1];
      #pragma unroll
      for (int i=0;i<4;i++){
        float p = Ps[(r0+i)*65 + e];
        a2[i][0] += p*v0; a2[i][1] += p*v1;
      }
    }
    #pragma unroll
    for (int i=0;i<4;i++){
      size_t o = base + (size_t)(r0+i)*TSEQ + t0 + tc;
      y[o]   = a2[i][0] + x[o];
      y[o+1] = a2[i][1] + x[o+1];
    }
    __syncthreads();
  }
}

// ------------------------- launch ------------------------------------------
static void launch_gemm(const float* A, const float* Bt, const float* bias,
                        const float* R, float* C, int M, int N, int K,
                        int act, int conv, int rnd){
  dim3 grid(N/BN, M/BM);
  gemm_kernel<<<grid, 256, GEMM_SMEM>>>(A, Bt, bias, R, C, M, N, K, act, conv, rnd);
}
static void launch_tcopy(const float* src, float* dst, int R, int C){
  dim3 grid(C/32, R/32), block(32,8);
  tcopy_kernel<<<grid, block>>>(src, dst, R, C);
}

extern "C" void kernel_launch(void* const* d_in, const int* in_sizes, int n_in,
                              void* d_out, int out_size) {
  const float* x       = (const float*)d_in[0];
  const float* q_w     = (const float*)d_in[1];
  const float* q_b     = (const float*)d_in[2];
  const float* k_w     = (const float*)d_in[3];
  const float* k_b     = (const float*)d_in[4];
  const float* v_w     = (const float*)d_in[5];
  const float* v_b     = (const float*)d_in[6];
  const float* temp    = (const float*)d_in[7];
  const float* ln1_w   = (const float*)d_in[8];
  const float* ln1_b   = (const float*)d_in[9];
  const float* ln2_w   = (const float*)d_in[10];
  const float* ln2_b   = (const float*)d_in[11];
  const float* ln3_w   = (const float*)d_in[12];
  const float* ln3_b   = (const float*)d_in[13];
  const float* ln4_w   = (const float*)d_in[14];
  const float* ln4_b   = (const float*)d_in[15];
  const float* lin1_w  = (const float*)d_in[16];
  const float* lin1_b  = (const float*)d_in[17];
  const float* lin2_w  = (const float*)d_in[18];
  const float* lin2_b  = (const float*)d_in[19];
  const float* mlp1_w1 = (const float*)d_in[20];
  const float* mlp1_b1 = (const float*)d_in[21];
  const float* mlp1_w2 = (const float*)d_in[22];
  const float* mlp1_b2 = (const float*)d_in[23];
  const float* mlp2_w1 = (const float*)d_in[24];
  const float* mlp2_b1 = (const float*)d_in[25];
  const float* mlp2_w2 = (const float*)d_in[26];
  const float* mlp2_b2 = (const float*)d_in[27];
  const float* conv1_w = (const float*)d_in[28];
  const float* conv1_b = (const float*)d_in[29];
  const float* conv2_w = (const float*)d_in[30];
  const float* conv2_b = (const float*)d_in[31];
  float* out = (float*)d_out;

  cudaFuncSetAttribute(gemm_kernel, cudaFuncAttributeMaxDynamicSharedMemorySize, GEMM_SMEM);

  float *p_ln, *p_q, *p_k, *p_v, *p_y, *p_y2, *p_dy, *p_wide;
  float *p_MT, *p_MinvA, *p_W1fT, *p_W2fT, *p_b2f, *p_Bc1t, *p_Bc2t;
  float *p_qwt, *p_kwt, *p_vwt, *p_lin1t, *p_lin2r, *p_m11t, *p_m12t, *p_m21t, *p_m22t;
  cudaGetSymbolAddress((void**)&p_ln,   g_ln);
  cudaGetSymbolAddress((void**)&p_q,    g_q);
  cudaGetSymbolAddress((void**)&p_k,    g_k);
  cudaGetSymbolAddress((void**)&p_v,    g_v);
  cudaGetSymbolAddress((void**)&p_y,    g_y);
  cudaGetSymbolAddress((void**)&p_y2,   g_y2);
  cudaGetSymbolAddress((void**)&p_dy,   g_dy);
  cudaGetSymbolAddress((void**)&p_wide, g_wide);
  cudaGetSymbolAddress((void**)&p_MT,   g_MT);
  cudaGetSymbolAddress((void**)&p_MinvA,g_MinvA);
  cudaGetSymbolAddress((void**)&p_W1fT, g_W1fT);
  cudaGetSymbolAddress((void**)&p_W2fT, g_W2fT);
  cudaGetSymbolAddress((void**)&p_b2f,  g_b2f);
  cudaGetSymbolAddress((void**)&p_Bc1t, g_Bc1t);
  cudaGetSymbolAddress((void**)&p_Bc2t, g_Bc2t);
  cudaGetSymbolAddress((void**)&p_qwt,  g_qwt);
  cudaGetSymbolAddress((void**)&p_kwt,  g_kwt);
  cudaGetSymbolAddress((void**)&p_vwt,  g_vwt);
  cudaGetSymbolAddress((void**)&p_lin1t,g_lin1t);
  cudaGetSymbolAddress((void**)&p_lin2r,g_lin2r);
  cudaGetSymbolAddress((void**)&p_m11t, g_m11t);
  cudaGetSymbolAddress((void**)&p_m12t, g_m12t);
  cudaGetSymbolAddress((void**)&p_m21t, g_m21t);
  cudaGetSymbolAddress((void**)&p_m22t, g_m22t);

  // attention block first (launch #5 = gemm K for ncu capture)
  ln_kernel<<<TOK, 256>>>(x, ln1_w, ln1_b, p_ln);          // 0
  launch_tcopy(q_w, p_qwt, DMODEL, DMODEL);                // 1
  launch_tcopy(k_w, p_kwt, DMODEL, DMODEL);                // 2
  launch_tcopy(v_w, p_vwt, DMODEL, DMODEL);                // 3
  launch_gemm(p_ln, p_qwt, q_b, nullptr, p_q, TOK, DMODEL, DMODEL, 0, 0, 0);  // 4
  launch_gemm(p_ln, p_kwt, k_b, nullptr, p_k, TOK, DMODEL, DMODEL, 0, 0, 0);  // 5
  launch_gemm(p_ln, p_vwt, v_b, nullptr, p_v, TOK, DMODEL, DMODEL, 0, 0, 0);  // 6
  attn_kernel<<<512, 256>>>(p_q, p_k, p_v, temp, x, p_y);  // 7

  // prep: DCT folds + weight transposes + conv packs
  build_dct_kernel<<<4096, 256>>>();
  launch_tcopy(lin1_w, p_lin1t, DMODEL, DFF);      // lin1^T [2048][1024]
  rcopy_kernel<<<(DFF*DMODEL)/1024, 256>>>(lin2_w, p_lin2r);
  launch_tcopy(mlp1_w1, p_m11t, DMODEL, DFF);
  launch_tcopy(mlp1_w2, p_m12t, DFF, DMODEL);
  launch_tcopy(mlp2_w1, p_m21t, DMODEL, DFF);
  launch_tcopy(mlp2_w2, p_m22t, DFF, DMODEL);
  pack_conv_kernel<<<12288, 256>>>(conv1_w, p_Bc1t);
  pack_conv_kernel<<<12288, 256>>>(conv2_w, p_Bc2t);
  // W1fT[j][i] = sum_k lin1t[j][k]*MT[i][k]   (A=lin1t, Bt=MT)
  launch_gemm(p_lin1t, p_MT, nullptr, nullptr, p_W1fT, DFF, DMODEL, DMODEL, 0, 0, 1);
  // W2fT[n][k2] = sum_k MinvA[n][k]*lin2r[k2][k]   (A=MinvA, Bt=lin2r)
  launch_gemm(p_MinvA, p_lin2r, nullptr, nullptr, p_W2fT, DMODEL, DFF, DMODEL, 0, 0, 1);
  fold_bias_kernel<<<DMODEL, 256>>>(lin2_b);

  // DCT-folded MLP
  ln_kernel<<<TOK, 256>>>(p_y, ln2_w, ln2_b, p_ln);
  launch_gemm(p_ln,   p_W1fT, lin1_b, nullptr, p_wide, TOK, DFF,    DMODEL, 1, 0, 1);
  launch_gemm(p_wide, p_W2fT, p_b2f,  nullptr, p_dy,   TOK, DMODEL, DFF,    0, 0, 1);

  // mlp1(d_y) + y
  launch_gemm(p_dy,   p_m11t, mlp1_b1, nullptr, p_wide, TOK, DFF,    DMODEL, 1, 0, 1);
  launch_gemm(p_wide, p_m12t, mlp1_b2, p_y,     p_y2,   TOK, DMODEL, DFF,    0, 0, 0);

  // mlp2(ln3(y)) added
  ln_kernel<<<TOK, 256>>>(p_y, ln3_w, ln3_b, p_ln);
  launch_gemm(p_ln,   p_m21t, mlp2_b1, nullptr, p_wide, TOK, DFF,    DMODEL, 1, 0, 1);
  launch_gemm(p_wide, p_m22t, mlp2_b2, p_y2,    p_y2,   TOK, DMODEL, DFF,    0, 0, 0);

  // conv path (shifted GEMMs, K=3072), silu between; final residual y2
  ln_kernel<<<TOK, 256>>>(p_y2, ln4_w, ln4_b, p_ln);
  launch_gemm(p_ln, p_Bc1t, conv1_b, nullptr, p_q, TOK, DMODEL, 3*DMODEL, 2, 1, 1);
  launch_gemm(p_q,  p_Bc2t, conv2_b, p_y2,    out, TOK, DMODEL, 3*DMODEL, 0, 1, 0);
}

// round 7
// speedup vs baseline: 1.7038x; 1.6601x over previous
#include <cuda_runtime.h>
#include <cuda_fp16.h>
#include <math.h>
#include <stdint.h>

#define TOK    16384
#define DMODEL 1024
#define DFF    2048
#define TSEQ   512
#define TDSZ   (TSEQ*DMODEL)

// ------------------------- scratch (device globals; no allocs) -------------
__device__ __half g_ln  [TOK*DMODEL];        // LN outputs (GEMM A)
__device__ __half g_wide[TOK*DFF];           // wide intermediates (GEMM A)
__device__ __half g_dy  [TOK*DMODEL];
__device__ __half g_c1  [TOK*DMODEL];        // conv1 silu output
__device__ float  g_q   [TOK*DMODEL];
__device__ float  g_k   [TOK*DMODEL];
__device__ float  g_v   [TOK*DMODEL];
__device__ float  g_y   [TOK*DMODEL];
__device__ float  g_y2  [TOK*DMODEL];
__device__ __half g_MT   [DMODEL*DMODEL];    // MT[n][k] = M[k][n]
__device__ __half g_MinvA[DMODEL*DMODEL];    // Minv[n][k]
__device__ __half g_W1fT [DFF*DMODEL];
__device__ __half g_W2fT [DMODEL*DFF];
__device__ float  g_b2f  [DMODEL];
__device__ __half g_Bc1t [DMODEL*3*DMODEL];  // [o][r*1024+i]
__device__ __half g_Bc2t [DMODEL*3*DMODEL];
__device__ __half g_qwt  [DMODEL*DMODEL];
__device__ __half g_kwt  [DMODEL*DMODEL];
__device__ __half g_vwt  [DMODEL*DMODEL];
__device__ __half g_lin1t[DFF*DMODEL];
__device__ __half g_lin2r[DFF*DMODEL];
__device__ __half g_m11t [DFF*DMODEL];
__device__ __half g_m12t [DMODEL*DFF];
__device__ __half g_m21t [DFF*DMODEL];
__device__ __half g_m22t [DMODEL*DFF];

// ------------------------- helpers ----------------------------------------
__device__ __forceinline__ void mma16(float* d, const uint32_t* a, const uint32_t* b){
  asm volatile(
    "mma.sync.aligned.m16n8k16.row.col.f32.f16.f16.f32 "
    "{%0,%1,%2,%3}, {%4,%5,%6,%7}, {%8,%9}, {%0,%1,%2,%3};"
    : "+f"(d[0]), "+f"(d[1]), "+f"(d[2]), "+f"(d[3])
    : "r"(a[0]), "r"(a[1]), "r"(a[2]), "r"(a[3]), "r"(b[0]), "r"(b[1]));
}
__device__ __forceinline__ void cp16(void* sdst, const void* gsrc, bool pred){
  uint32_t s = (uint32_t)__cvta_generic_to_shared(sdst);
  int n = pred ? 16 : 0;
  asm volatile("cp.async.cg.shared.global [%0], [%1], 16, %2;" :: "r"(s), "l"(gsrc), "r"(n));
}
__device__ __forceinline__ void cp_commit(){ asm volatile("cp.async.commit_group;"); }
template<int N> __device__ __forceinline__ void cp_wait(){
  asm volatile("cp.async.wait_group %0;" :: "n"(N));
}
__device__ __forceinline__ float gelu_f(float x){
  return 0.5f*x*(1.f + erff(x*0.70710678118654752f));
}
__device__ __forceinline__ float silu_f(float x){ return x/(1.f+expf(-x)); }

// ------------------------- prep kernels ------------------------------------
__global__ void build_dct_kernel(){
  int idx = blockIdx.x*256 + threadIdx.x;   // < 1024*1024
  int i = idx >> 10, j = idx & 1023;        // i = n, j = k
  const float c = 3.14159265358979323846f/2048.f;
  int m1 = ((2*i+1)*j) & 4095;
  g_MT[idx] = __float2half(2.f*cosf((float)m1 * c));
  float sc = (j==0) ? (0.5f/1024.f) : (1.f/1024.f);
  g_MinvA[idx] = __float2half(cosf((float)m1 * c) * sc);
}

// conv w (O,I,3) -> Bt[o][r*1024+i]
__global__ void pack_conv_kernel(const float* __restrict__ w, __half* __restrict__ Bt){
  int idx = blockIdx.x*256 + threadIdx.x;   // < 3*1024*1024
  int o = idx / 3072;
  int rem = idx - o*3072;
  int r = rem >> 10;
  int i = rem & 1023;
  Bt[idx] = __float2half(w[((o<<10) + i)*3 + r]);
}

// tiled transpose + f16: src[R][C] -> dst[C][R]
__global__ void tcopy_kernel(const float* __restrict__ src, __half* __restrict__ dst,
                             int R, int C){
  __shared__ float t[32][33];
  int bx = blockIdx.x*32, by = blockIdx.y*32;
  int x = threadIdx.x, y = threadIdx.y;     // block (32,8)
  #pragma unroll
  for (int j=0;j<32;j+=8)
    t[y+j][x] = src[(size_t)(by+y+j)*C + bx + x];
  __syncthreads();
  #pragma unroll
  for (int j=0;j<32;j+=8)
    dst[(size_t)(bx+y+j)*R + by + x] = __float2half(t[x][y+j]);
}

// elementwise f16 copy
__global__ void rcopy_kernel(const float* __restrict__ src, __half* __restrict__ dst){
  int idx = blockIdx.x*256 + threadIdx.x;
  float4 v = *(const float4*)(src + idx*4);
  __half2 h0 = __floats2half2_rn(v.x, v.y);
  __half2 h1 = __floats2half2_rn(v.z, v.w);
  *(uint2*)(dst + idx*4) = make_uint2(*(uint32_t*)&h0, *(uint32_t*)&h1);
}

// b2f[n] = sum_k lin2_b[k] * Minv[n][k]
__global__ __launch_bounds__(256) void fold_bias_kernel(const float* __restrict__ b2){
  __shared__ float red[8];
  const int n = blockIdx.x, tid = threadIdx.x;
  const int lane = tid & 31, warp = tid >> 5;
  float s = 0.f;
  for (int k = tid; k < 1024; k += 256) s += b2[k]*__half2float(g_MinvA[(n<<10)+k]);
  #pragma unroll
  for (int o=16;o;o>>=1) s += __shfl_xor_sync(0xffffffffu,s,o);
  if (lane==0) red[warp]=s;
  __syncthreads();
  if (tid==0){
    float t=0.f;
    #pragma unroll
    for (int w2=0;w2<8;w2++) t+=red[w2];
    g_b2f[n]=t;
  }
}

// ------------------------- LayerNorm (f16 out) ------------------------------
__global__ __launch_bounds__(256) void ln_kernel(
    const float* __restrict__ x, const float* __restrict__ gw,
    const float* __restrict__ gb, __half* __restrict__ out)
{
  __shared__ float rs[8], rq[8], mv[2];
  const int row = blockIdx.x, tid = threadIdx.x;
  const int lane = tid & 31, warp = tid >> 5;
  const float4 xv = *(const float4*)(x + (size_t)row*1024 + tid*4);
  float s = xv.x+xv.y+xv.z+xv.w;
  float q = xv.x*xv.x+xv.y*xv.y+xv.z*xv.z+xv.w*xv.w;
  #pragma unroll
  for (int o=16;o;o>>=1){ s += __shfl_xor_sync(0xffffffffu,s,o); q += __shfl_xor_sync(0xffffffffu,q,o); }
  if (lane==0){ rs[warp]=s; rq[warp]=q; }
  __syncthreads();
  if (tid==0){
    float ss=0.f, qq=0.f;
    #pragma unroll
    for (int w2=0;w2<8;w2++){ ss+=rs[w2]; qq+=rq[w2]; }
    float m = ss*(1.f/1024.f);
    float var = qq*(1.f/1024.f) - m*m;
    mv[0]=m; mv[1]=rsqrtf(var + 1e-5f);
  }
  __syncthreads();
  const float m = mv[0], inv = mv[1];
  const float4 g4 = *(const float4*)(gw + tid*4);
  const float4 b4 = *(const float4*)(gb + tid*4);
  __half2 h0 = __floats2half2_rn((xv.x-m)*inv*g4.x + b4.x, (xv.y-m)*inv*g4.y + b4.y);
  __half2 h1 = __floats2half2_rn((xv.z-m)*inv*g4.z + b4.z, (xv.w-m)*inv*g4.w + b4.w);
  *(uint2*)(out + (size_t)row*1024 + tid*4) = make_uint2(*(uint32_t*)&h0, *(uint32_t*)&h1);
}

// ------------------------- fp16 GEMM (m16n8k16, f32 accum) ------------------
// C = act(A@Bt^T + bias) [+R].  A: MxK half row-major (lda=K or DMODEL in
// conv mode), Bt: NxK half row-major.  C float (ohalf=0) or half (ohalf=1).
// conv mode: K=3*1024; r=k>>10 selects time-shift (r-1) on A rows, masked at
// T=512 sequence boundaries (masked loads zero-fill).
#define BM 128
#define BN 128
#define BK 32
#define ASTRH 40
#define BTSTRH 40
#define AELE (BM*ASTRH)
#define BELE (BN*BTSTRH)

__device__ __forceinline__ void gemm_load_stage(
    const __half* __restrict__ A, const __half* __restrict__ Bt,
    __half* asb, __half* bsb, int tid, int bm, int bn, int K, int lda,
    int conv, int kt)
{
  const int k0 = kt*BK;
  int roff = 0, kk0 = k0;
  if (conv){ roff = (k0 >> 10) - 1; kk0 = k0 & 1023; }
  #pragma unroll
  for (int j=0;j<2;j++){
    int i = tid + j*256;
    int ar = i >> 2, ac = (i & 3)*8;
    int grow = bm + ar;
    bool pr = true; int srow = grow;
    if (conv){
      int tt = grow & (TSEQ-1);
      int tp = tt + roff;
      pr = (tp >= 0) && (tp < TSEQ);
      srow = pr ? (grow + roff) : grow;
    }
    cp16(asb + ar*ASTRH + ac, A + (size_t)srow*lda + kk0 + ac, pr);
  }
  #pragma unroll
  for (int j=0;j<2;j++){
    int i = tid + j*256;
    int br = i >> 2, bc = (i & 3)*8;
    cp16(bsb + br*BTSTRH + bc, Bt + (size_t)(bn+br)*K + k0 + bc, true);
  }
  cp_commit();
}

__global__ __launch_bounds__(256) void gemm_kernel(
    const __half* __restrict__ A, const __half* __restrict__ Bt,
    const float* __restrict__ bias, const float* __restrict__ Rres,
    void* __restrict__ Cp, int M, int N, int K, int act, int conv, int ohalf)
{
  __shared__ __align__(16) __half As[2*AELE];
  __shared__ __align__(16) __half Bs[2*BELE];
  const int tid = threadIdx.x;
  const int bm = blockIdx.y*BM, bn = blockIdx.x*BN;
  const int lane = tid & 31, warp = tid >> 5;
  const int wm = warp >> 1, wn = warp & 1;
  const int rowW = wm*32, colW = wn*64;
  const int lda = conv ? DMODEL : K;
  const int KT = K / BK;
  const int q2 = (lane & 3)*2;
  const int aoff = (rowW + (lane>>2))*ASTRH + q2;
  const int boff = (colW + (lane>>2))*BTSTRH + q2;

  float acc[2][8][4];
  #pragma unroll
  for (int a1=0;a1<2;a1++)
    #pragma unroll
    for (int a2=0;a2<8;a2++)
      #pragma unroll
      for (int a3=0;a3<4;a3++) acc[a1][a2][a3]=0.f;

  gemm_load_stage(A,Bt,As,Bs,tid,bm,bn,K,lda,conv,0);
  for (int kt=0; kt<KT; kt++){
    const int cur = kt & 1;
    if (kt+1 < KT){
      gemm_load_stage(A,Bt,As+(cur^1)*AELE,Bs+(cur^1)*BELE,tid,bm,bn,K,lda,conv,kt+1);
      cp_wait<1>();
    } else {
      cp_wait<0>();
    }
    __syncthreads();
    const __half* asb = As + cur*AELE;
    const __half* bsb = Bs + cur*BELE;
    #pragma unroll
    for (int ks=0; ks<2; ks++){
      const int kb = ks*16;
      uint32_t af[2][4], bf[8][2];
      #pragma unroll
      for (int mt=0; mt<2; mt++){
        const __half* ap = asb + aoff + mt*(16*ASTRH) + kb;
        af[mt][0] = *(const uint32_t*)(ap);
        af[mt][1] = *(const uint32_t*)(ap + 8*ASTRH);
        af[mt][2] = *(const uint32_t*)(ap + 8);
        af[mt][3] = *(const uint32_t*)(ap + 8*ASTRH + 8);
      }
      #pragma unroll
      for (int nt=0; nt<8; nt++){
        const __half* bp = bsb + boff + nt*(8*BTSTRH) + kb;
        bf[nt][0] = *(const uint32_t*)(bp);
        bf[nt][1] = *(const uint32_t*)(bp + 8);
      }
      #pragma unroll
      for (int mt=0; mt<2; mt++)
        #pragma unroll
        for (int nt=0; nt<8; nt++)
          mma16(acc[mt][nt], af[mt], bf[nt]);
    }
    __syncthreads();
  }

  float* Cf = (float*)Cp;
  __half* Ch = (__half*)Cp;
  #pragma unroll
  for (int mt=0; mt<2; mt++){
    const int r0 = bm + rowW + mt*16 + (lane>>2);
    #pragma unroll
    for (int nt=0; nt<8; nt++){
      const int c0 = bn + colW + nt*8 + (lane&3)*2;
      const float bb0 = bias ? bias[c0]   : 0.f;
      const float bb1 = bias ? bias[c0+1] : 0.f;
      #pragma unroll
      for (int rr=0; rr<2; rr++){
        const int r = r0 + rr*8;
        float v0 = acc[mt][nt][rr*2+0] + bb0;
        float v1 = acc[mt][nt][rr*2+1] + bb1;
        if (act==1){ v0 = gelu_f(v0); v1 = gelu_f(v1); }
        else if (act==2){ v0 = silu_f(v0); v1 = silu_f(v1); }
        if (Rres){
          const float* rp = Rres + (size_t)r*N + c0;
          v0 += rp[0]; v1 += rp[1];
        }
        if (ohalf){
          __half2 h = __floats2half2_rn(v0, v1);
          *(__half2*)(Ch + (size_t)r*N + c0) = h;
        } else {
          *(float2*)(Cf + (size_t)r*N + c0) = make_float2(v0, v1);
        }
      }
    }
  }
}

// ------------------------- channel attention -------------------------------
// Per (b,h): Q,K,V contiguous 64x512 row-major (flat view); S = QK^T*temp[h];
// softmax rows; out = S@V; y = out + x.
__global__ __launch_bounds__(256) void attn_kernel(
    const float* __restrict__ q, const float* __restrict__ k,
    const float* __restrict__ v, const float* __restrict__ temp,
    const float* __restrict__ x, float* __restrict__ y)
{
  __shared__ float Qs[64*36];
  __shared__ float Ks[64*36];
  __shared__ float Ps[64*65];
  const int bh = blockIdx.x;
  const int b = bh >> 4, h = bh & 15;
  const size_t base = (size_t)b*TDSZ + (size_t)h*(64*TSEQ);
  const float* Q  = q + base;
  const float* Kp = k + base;
  const float* V  = v + base;
  const int tid = threadIdx.x;
  const int tx = tid & 15, ty = tid >> 4;
  const int r0 = ty*4, c0 = tx*4;

  float acc[16];
  #pragma unroll
  for (int i2=0;i2<16;i2++) acc[i2]=0.f;

  for (int t0 = 0; t0 < TSEQ; t0 += 32){
    #pragma unroll
    for (int j=0;j<2;j++){
      int i = tid + j*256;
      int row = i >> 3, col = (i & 7)*4;
      *(float4*)(Qs + row*36 + col) = *(const float4*)(Q  + row*TSEQ + t0 + col);
      *(float4*)(Ks + row*36 + col) = *(const float4*)(Kp + row*TSEQ + t0 + col);
    }
    __syncthreads();
    for (int kk=0; kk<32; kk++){
      float qv[4], kv[4];
      #pragma unroll
      for (int i=0;i<4;i++) qv[i] = Qs[(r0+i)*36 + kk];
      #pragma unroll
      for (int j=0;j<4;j++) kv[j] = Ks[(c0+j)*36 + kk];
      #pragma unroll
      for (int i=0;i<4;i++)
        #pragma unroll
        for (int j=0;j<4;j++) acc[i*4+j] += qv[i]*kv[j];
    }
    __syncthreads();
  }
  const float tmp = temp[h];
  #pragma unroll
  for (int i=0;i<4;i++)
    #pragma unroll
    for (int j=0;j<4;j++) Ps[(r0+i)*65 + c0 + j] = acc[i*4+j]*tmp;
  __syncthreads();

  if (tid < 64){
    float* row = Ps + tid*65;
    float m = row[0];
    for (int e=1;e<64;e++) m = fmaxf(m, row[e]);
    float s = 0.f;
    for (int e=0;e<64;e++){ float ev = expf(row[e]-m); row[e]=ev; s+=ev; }
    float inv = 1.f/s;
    for (int e=0;e<64;e++) row[e] *= inv;
  }
  __syncthreads();

  const int tc = tx*2;
  for (int t0 = 0; t0 < TSEQ; t0 += 32){
    #pragma unroll
    for (int j=0;j<2;j++){
      int i = tid + j*256;
      int row = i >> 3, col = (i & 7)*4;
      *(float4*)(Qs + row*36 + col) = *(const float4*)(V + row*TSEQ + t0 + col);
    }
    __syncthreads();
    float a2[4][2];
    #pragma unroll
    for (int i=0;i<4;i++){ a2[i][0]=0.f; a2[i][1]=0.f; }
    for (int e=0;e<64;e++){
      float v0 = Qs[e*36 + tc], v1 = Qs[e*36 + tc + 1];
      #pragma unroll
      for (int i=0;i<4;i++){
        float p = Ps[(r0+i)*65 + e];
        a2[i][0] += p*v0; a2[i][1] += p*v1;
      }
    }
    #pragma unroll
    for (int i=0;i<4;i++){
      size_t o = base + (size_t)(r0+i)*TSEQ + t0 + tc;
      y[o]   = a2[i][0] + x[o];
      y[o+1] = a2[i][1] + x[o+1];
    }
    __syncthreads();
  }
}

// ------------------------- launch ------------------------------------------
static void launch_gemm(const __half* A, const __half* Bt, const float* bias,
                        const float* R, void* C, int M, int N, int K,
                        int act, int conv, int ohalf){
  dim3 grid(N/BN, M/BM);
  gemm_kernel<<<grid, 256>>>(A, Bt, bias, R, C, M, N, K, act, conv, ohalf);
}
static void launch_tcopy(const float* src, __half* dst, int R, int C){
  dim3 grid(C/32, R/32), block(32,8);
  tcopy_kernel<<<grid, block>>>(src, dst, R, C);
}

extern "C" void kernel_launch(void* const* d_in, const int* in_sizes, int n_in,
                              void* d_out, int out_size) {
  const float* x       = (const float*)d_in[0];
  const float* q_w     = (const float*)d_in[1];
  const float* q_b     = (const float*)d_in[2];
  const float* k_w     = (const float*)d_in[3];
  const float* k_b     = (const float*)d_in[4];
  const float* v_w     = (const float*)d_in[5];
  const float* v_b     = (const float*)d_in[6];
  const float* temp    = (const float*)d_in[7];
  const float* ln1_w   = (const float*)d_in[8];
  const float* ln1_b   = (const float*)d_in[9];
  const float* ln2_w   = (const float*)d_in[10];
  const float* ln2_b   = (const float*)d_in[11];
  const float* ln3_w   = (const float*)d_in[12];
  const float* ln3_b   = (const float*)d_in[13];
  const float* ln4_w   = (const float*)d_in[14];
  const float* ln4_b   = (const float*)d_in[15];
  const float* lin1_w  = (const float*)d_in[16];
  const float* lin1_b  = (const float*)d_in[17];
  const float* lin2_w  = (const float*)d_in[18];
  const float* lin2_b  = (const float*)d_in[19];
  const float* mlp1_w1 = (const float*)d_in[20];
  const float* mlp1_b1 = (const float*)d_in[21];
  const float* mlp1_w2 = (const float*)d_in[22];
  const float* mlp1_b2 = (const float*)d_in[23];
  const float* mlp2_w1 = (const float*)d_in[24];
  const float* mlp2_b1 = (const float*)d_in[25];
  const float* mlp2_w2 = (const float*)d_in[26];
  const float* mlp2_b2 = (const float*)d_in[27];
  const float* conv1_w = (const float*)d_in[28];
  const float* conv1_b = (const float*)d_in[29];
  const float* conv2_w = (const float*)d_in[30];
  const float* conv2_b = (const float*)d_in[31];
  float* out = (float*)d_out;

  __half *p_ln, *p_wide, *p_dy, *p_c1;
  float  *p_q, *p_k, *p_v, *p_y, *p_y2, *p_b2f;
  __half *p_MT, *p_MinvA, *p_W1fT, *p_W2fT, *p_Bc1t, *p_Bc2t;
  __half *p_qwt, *p_kwt, *p_vwt, *p_lin1t, *p_lin2r, *p_m11t, *p_m12t, *p_m21t, *p_m22t;
  cudaGetSymbolAddress((void**)&p_ln,   g_ln);
  cudaGetSymbolAddress((void**)&p_wide, g_wide);
  cudaGetSymbolAddress((void**)&p_dy,   g_dy);
  cudaGetSymbolAddress((void**)&p_c1,   g_c1);
  cudaGetSymbolAddress((void**)&p_q,    g_q);
  cudaGetSymbolAddress((void**)&p_k,    g_k);
  cudaGetSymbolAddress((void**)&p_v,    g_v);
  cudaGetSymbolAddress((void**)&p_y,    g_y);
  cudaGetSymbolAddress((void**)&p_y2,   g_y2);
  cudaGetSymbolAddress((void**)&p_b2f,  g_b2f);
  cudaGetSymbolAddress((void**)&p_MT,   g_MT);
  cudaGetSymbolAddress((void**)&p_MinvA,g_MinvA);
  cudaGetSymbolAddress((void**)&p_W1fT, g_W1fT);
  cudaGetSymbolAddress((void**)&p_W2fT, g_W2fT);
  cudaGetSymbolAddress((void**)&p_Bc1t, g_Bc1t);
  cudaGetSymbolAddress((void**)&p_Bc2t, g_Bc2t);
  cudaGetSymbolAddress((void**)&p_qwt,  g_qwt);
  cudaGetSymbolAddress((void**)&p_kwt,  g_kwt);
  cudaGetSymbolAddress((void**)&p_vwt,  g_vwt);
  cudaGetSymbolAddress((void**)&p_lin1t,g_lin1t);
  cudaGetSymbolAddress((void**)&p_lin2r,g_lin2r);
  cudaGetSymbolAddress((void**)&p_m11t, g_m11t);
  cudaGetSymbolAddress((void**)&p_m12t, g_m12t);
  cudaGetSymbolAddress((void**)&p_m21t, g_m21t);
  cudaGetSymbolAddress((void**)&p_m22t, g_m22t);

  // attention block; launch index 3 = Q-projection GEMM (profiling target)
  ln_kernel<<<TOK, 256>>>(x, ln1_w, ln1_b, p_ln);                               // 0
  launch_tcopy(q_w, p_qwt, DMODEL, DMODEL);                                     // 1
  launch_tcopy(k_w, p_kwt, DMODEL, DMODEL);                                     // 2
  launch_gemm(p_ln, p_qwt, q_b, nullptr, p_q, TOK, DMODEL, DMODEL, 0, 0, 0);    // 3
  launch_tcopy(v_w, p_vwt, DMODEL, DMODEL);                                     // 4
  launch_gemm(p_ln, p_kwt, k_b, nullptr, p_k, TOK, DMODEL, DMODEL, 0, 0, 0);
  launch_gemm(p_ln, p_vwt, v_b, nullptr, p_v, TOK, DMODEL, DMODEL, 0, 0, 0);
  attn_kernel<<<512, 256>>>(p_q, p_k, p_v, temp, x, p_y);

  // prep: DCT folds + weight transposes + conv packs
  build_dct_kernel<<<4096, 256>>>();
  launch_tcopy(lin1_w, p_lin1t, DMODEL, DFF);
  rcopy_kernel<<<(DFF*DMODEL)/1024, 256>>>(lin2_w, p_lin2r);
  launch_tcopy(mlp1_w1, p_m11t, DMODEL, DFF);
  launch_tcopy(mlp1_w2, p_m12t, DFF, DMODEL);
  launch_tcopy(mlp2_w1, p_m21t, DMODEL, DFF);
  launch_tcopy(mlp2_w2, p_m22t, DFF, DMODEL);
  pack_conv_kernel<<<12288, 256>>>(conv1_w, p_Bc1t);
  pack_conv_kernel<<<12288, 256>>>(conv2_w, p_Bc2t);
  // W1fT[j][i] = sum_k lin1t[j][k]*MT[i][k]
  launch_gemm(p_lin1t, p_MT,    nullptr, nullptr, p_W1fT, DFF,    DMODEL, DMODEL, 0, 0, 1);
  // W2fT[n][k2] = sum_k MinvA[n][k]*lin2r[k2][k]
  launch_gemm(p_MinvA, p_lin2r, nullptr, nullptr, p_W2fT, DMODEL, DFF,    DMODEL, 0, 0, 1);
  fold_bias_kernel<<<DMODEL, 256>>>(lin2_b);

  // DCT-folded MLP
  ln_kernel<<<TOK, 256>>>(p_y, ln2_w, ln2_b, p_ln);
  launch_gemm(p_ln,   p_W1fT, lin1_b, nullptr, p_wide, TOK, DFF,    DMODEL, 1, 0, 1);
  launch_gemm(p_wide, p_W2fT, p_b2f,  nullptr, p_dy,   TOK, DMODEL, DFF,    0, 0, 1);

  // mlp1(d_y) + y
  launch_gemm(p_dy,   p_m11t, mlp1_b1, nullptr, p_wide, TOK, DFF,    DMODEL, 1, 0, 1);
  launch_gemm(p_wide, p_m12t, mlp1_b2, p_y,     p_y2,   TOK, DMODEL, DFF,    0, 0, 0);

  // mlp2(ln3(y)) added
  ln_kernel<<<TOK, 256>>>(p_y, ln3_w, ln3_b, p_ln);
  launch_gemm(p_ln,   p_m21t, mlp2_b1, nullptr, p_wide, TOK, DFF,    DMODEL, 1, 0, 1);
  launch_gemm(p_wide, p_m22t, mlp2_b2, p_y2,    p_y2,   TOK, DMODEL, DFF,    0, 0, 0);

  // conv path (shifted GEMMs, K=3072), silu between; final residual y2
  ln_kernel<<<TOK, 256>>>(p_y2, ln4_w, ln4_b, p_ln);
  launch_gemm(p_ln, p_Bc1t, conv1_b, nullptr, p_c1, TOK, DMODEL, 3*DMODEL, 2, 1, 1);
  launch_gemm(p_c1, p_Bc2t, conv2_b, p_y2,    out,  TOK, DMODEL, 3*DMODEL, 0, 1, 0);
}

// round 8
// speedup vs baseline: 1.8389x; 1.0793x over previous
#include <cuda_runtime.h>
#include <cuda_fp16.h>
#include <math.h>
#include <stdint.h>

#define TOK    16384
#define DMODEL 1024
#define DFF    2048
#define TSEQ   512
#define TDSZ   (TSEQ*DMODEL)

// ------------------------- scratch (device globals; no allocs) -------------
__device__ __half g_ln  [TOK*DMODEL];
__device__ __half g_wide[TOK*DFF];
__device__ __half g_dy  [TOK*DMODEL];
__device__ __half g_c1  [TOK*DMODEL];
__device__ float  g_q   [TOK*DMODEL];
__device__ float  g_k   [TOK*DMODEL];
__device__ float  g_v   [TOK*DMODEL];
__device__ float  g_y   [TOK*DMODEL];
__device__ float  g_y2  [TOK*DMODEL];
__device__ __half g_MT   [DMODEL*DMODEL];
__device__ __half g_MinvA[DMODEL*DMODEL];
__device__ __half g_W1fT [DFF*DMODEL];
__device__ __half g_W2fT [DMODEL*DFF];
__device__ float  g_b2f  [DMODEL];
__device__ __half g_Bc1t [DMODEL*3*DMODEL];
__device__ __half g_Bc2t [DMODEL*3*DMODEL];
__device__ __half g_qwt  [DMODEL*DMODEL];
__device__ __half g_kwt  [DMODEL*DMODEL];
__device__ __half g_vwt  [DMODEL*DMODEL];
__device__ __half g_lin1t[DFF*DMODEL];
__device__ __half g_lin2r[DFF*DMODEL];
__device__ __half g_m11t [DFF*DMODEL];
__device__ __half g_m12t [DMODEL*DFF];
__device__ __half g_m21t [DFF*DMODEL];
__device__ __half g_m22t [DMODEL*DFF];

// ------------------------- helpers ----------------------------------------
__device__ __forceinline__ void mma16(float* d, const uint32_t* a, const uint32_t* b){
  asm volatile(
    "mma.sync.aligned.m16n8k16.row.col.f32.f16.f16.f32 "
    "{%0,%1,%2,%3}, {%4,%5,%6,%7}, {%8,%9}, {%0,%1,%2,%3};"
    : "+f"(d[0]), "+f"(d[1]), "+f"(d[2]), "+f"(d[3])
    : "r"(a[0]), "r"(a[1]), "r"(a[2]), "r"(a[3]), "r"(b[0]), "r"(b[1]));
}
#define LDSM4(r0,r1,r2,r3,addr) \
  asm volatile("ldmatrix.sync.aligned.m8n8.x4.shared.b16 {%0,%1,%2,%3}, [%4];" \
               : "=r"(r0), "=r"(r1), "=r"(r2), "=r"(r3) : "r"(addr))
__device__ __forceinline__ void cp16(void* sdst, const void* gsrc, bool pred){
  uint32_t s = (uint32_t)__cvta_generic_to_shared(sdst);
  int n = pred ? 16 : 0;
  asm volatile("cp.async.cg.shared.global [%0], [%1], 16, %2;" :: "r"(s), "l"(gsrc), "r"(n));
}
__device__ __forceinline__ void cp_commit(){ asm volatile("cp.async.commit_group;"); }
template<int N> __device__ __forceinline__ void cp_wait(){
  asm volatile("cp.async.wait_group %0;" :: "n"(N));
}
__device__ __forceinline__ float gelu_f(float x){
  return 0.5f*x*(1.f + erff(x*0.70710678118654752f));
}
__device__ __forceinline__ float silu_f(float x){ return x/(1.f+expf(-x)); }

// ------------------------- prep kernels ------------------------------------
__global__ void build_dct_kernel(){
  int idx = blockIdx.x*256 + threadIdx.x;
  int i = idx >> 10, j = idx & 1023;        // i = n, j = k
  const float c = 3.14159265358979323846f/2048.f;
  int m1 = ((2*i+1)*j) & 4095;
  g_MT[idx] = __float2half(2.f*cosf((float)m1 * c));
  float sc = (j==0) ? (0.5f/1024.f) : (1.f/1024.f);
  g_MinvA[idx] = __float2half(cosf((float)m1 * c) * sc);
}

__global__ void pack_conv_kernel(const float* __restrict__ w, __half* __restrict__ Bt){
  int idx = blockIdx.x*256 + threadIdx.x;
  int o = idx / 3072;
  int rem = idx - o*3072;
  int r = rem >> 10;
  int i = rem & 1023;
  Bt[idx] = __float2half(w[((o<<10) + i)*3 + r]);
}

__global__ void tcopy_kernel(const float* __restrict__ src, __half* __restrict__ dst,
                             int R, int C){
  __shared__ float t[32][33];
  int bx = blockIdx.x*32, by = blockIdx.y*32;
  int x = threadIdx.x, y = threadIdx.y;
  #pragma unroll
  for (int j=0;j<32;j+=8)
    t[y+j][x] = src[(size_t)(by+y+j)*C + bx + x];
  __syncthreads();
  #pragma unroll
  for (int j=0;j<32;j+=8)
    dst[(size_t)(bx+y+j)*R + by + x] = __float2half(t[x][y+j]);
}

__global__ void rcopy_kernel(const float* __restrict__ src, __half* __restrict__ dst){
  int idx = blockIdx.x*256 + threadIdx.x;
  float4 v = *(const float4*)(src + idx*4);
  __half2 h0 = __floats2half2_rn(v.x, v.y);
  __half2 h1 = __floats2half2_rn(v.z, v.w);
  *(uint2*)(dst + idx*4) = make_uint2(*(uint32_t*)&h0, *(uint32_t*)&h1);
}

__global__ __launch_bounds__(256) void fold_bias_kernel(const float* __restrict__ b2){
  __shared__ float red[8];
  const int n = blockIdx.x, tid = threadIdx.x;
  const int lane = tid & 31, warp = tid >> 5;
  float s = 0.f;
  for (int k = tid; k < 1024; k += 256) s += b2[k]*__half2float(g_MinvA[(n<<10)+k]);
  #pragma unroll
  for (int o=16;o;o>>=1) s += __shfl_xor_sync(0xffffffffu,s,o);
  if (lane==0) red[warp]=s;
  __syncthreads();
  if (tid==0){
    float t=0.f;
    #pragma unroll
    for (int w2=0;w2<8;w2++) t+=red[w2];
    g_b2f[n]=t;
  }
}

// ------------------------- LayerNorm (f16 out) ------------------------------
__global__ __launch_bounds__(256) void ln_kernel(
    const float* __restrict__ x, const float* __restrict__ gw,
    const float* __restrict__ gb, __half* __restrict__ out)
{
  __shared__ float rs[8], rq[8], mv[2];
  const int row = blockIdx.x, tid = threadIdx.x;
  const int lane = tid & 31, warp = tid >> 5;
  const float4 xv = *(const float4*)(x + (size_t)row*1024 + tid*4);
  float s = xv.x+xv.y+xv.z+xv.w;
  float q = xv.x*xv.x+xv.y*xv.y+xv.z*xv.z+xv.w*xv.w;
  #pragma unroll
  for (int o=16;o;o>>=1){ s += __shfl_xor_sync(0xffffffffu,s,o); q += __shfl_xor_sync(0xffffffffu,q,o); }
  if (lane==0){ rs[warp]=s; rq[warp]=q; }
  __syncthreads();
  if (tid==0){
    float ss=0.f, qq=0.f;
    #pragma unroll
    for (int w2=0;w2<8;w2++){ ss+=rs[w2]; qq+=rq[w2]; }
    float m = ss*(1.f/1024.f);
    float var = qq*(1.f/1024.f) - m*m;
    mv[0]=m; mv[1]=rsqrtf(var + 1e-5f);
  }
  __syncthreads();
  const float m = mv[0], inv = mv[1];
  const float4 g4 = *(const float4*)(gw + tid*4);
  const float4 b4 = *(const float4*)(gb + tid*4);
  __half2 h0 = __floats2half2_rn((xv.x-m)*inv*g4.x + b4.x, (xv.y-m)*inv*g4.y + b4.y);
  __half2 h1 = __floats2half2_rn((xv.z-m)*inv*g4.z + b4.z, (xv.w-m)*inv*g4.w + b4.w);
  *(uint2*)(out + (size_t)row*1024 + tid*4) = make_uint2(*(uint32_t*)&h0, *(uint32_t*)&h1);
}

// ------------------------- fp16 GEMM (m16n8k16, ldmatrix) -------------------
#define BM 128
#define BN 128
#define BK 32
#define ASTRH 40
#define BTSTRH 40
#define AELE (BM*ASTRH)
#define BELE (BN*BTSTRH)

__device__ __forceinline__ void gemm_load_stage(
    const __half* __restrict__ A, const __half* __restrict__ Bt,
    __half* asb, __half* bsb, int tid, int bm, int bn, int K, int lda,
    int conv, int kt)
{
  const int k0 = kt*BK;
  int roff = 0, kk0 = k0;
  if (conv){ roff = (k0 >> 10) - 1; kk0 = k0 & 1023; }
  #pragma unroll
  for (int j=0;j<2;j++){
    int i = tid + j*256;
    int ar = i >> 2, ac = (i & 3)*8;
    int grow = bm + ar;
    bool pr = true; int srow = grow;
    if (conv){
      int tt = grow & (TSEQ-1);
      int tp = tt + roff;
      pr = (tp >= 0) && (tp < TSEQ);
      srow = pr ? (grow + roff) : grow;
    }
    cp16(asb + ar*ASTRH + ac, A + (size_t)srow*lda + kk0 + ac, pr);
  }
  #pragma unroll
  for (int j=0;j<2;j++){
    int i = tid + j*256;
    int br = i >> 2, bc = (i & 3)*8;
    cp16(bsb + br*BTSTRH + bc, Bt + (size_t)(bn+br)*K + k0 + bc, true);
  }
  cp_commit();
}

__global__ __launch_bounds__(256) void gemm_kernel(
    const __half* __restrict__ A, const __half* __restrict__ Bt,
    const float* __restrict__ bias, const float* __restrict__ Rres,
    void* __restrict__ Cp, int M, int N, int K, int act, int conv, int ohalf)
{
  __shared__ __align__(16) __half As[2*AELE];
  __shared__ __align__(16) __half Bs[2*BELE];
  const int tid = threadIdx.x;
  const int bm = blockIdx.y*BM, bn = blockIdx.x*BN;
  const int lane = tid & 31, warp = tid >> 5;
  const int wm = warp >> 1, wn = warp & 1;
  const int rowW = wm*32, colW = wn*64;
  const int lda = conv ? DMODEL : K;
  const int KT = K / BK;

  // ldmatrix per-lane byte offsets
  const uint32_t As32 = (uint32_t)__cvta_generic_to_shared(As);
  const uint32_t Bs32 = (uint32_t)__cvta_generic_to_shared(Bs);
  // A tile mt: rows rowW+mt*16+(lane&15), k col (lane>>4)*8
  uint32_t aoffm[2];
  #pragma unroll
  for (int mt=0; mt<2; mt++)
    aoffm[mt] = (uint32_t)(((rowW + mt*16 + (lane & 15))*ASTRH + ((lane >> 4)*8))*2);
  // B pair p: rows colW+p*16+(lane&7)+((lane>>4)*8), k col ((lane>>3)&1)*8
  uint32_t boffp[4];
  #pragma unroll
  for (int p=0; p<4; p++)
    boffp[p] = (uint32_t)(((colW + p*16 + (lane & 7) + ((lane >> 4)*8))*BTSTRH
                          + (((lane >> 3) & 1)*8))*2);

  float acc[2][8][4];
  #pragma unroll
  for (int a1=0;a1<2;a1++)
    #pragma unroll
    for (int a2=0;a2<8;a2++)
      #pragma unroll
      for (int a3=0;a3<4;a3++) acc[a1][a2][a3]=0.f;

  gemm_load_stage(A,Bt,As,Bs,tid,bm,bn,K,lda,conv,0);
  for (int kt=0; kt<KT; kt++){
    const int cur = kt & 1;
    if (kt+1 < KT){
      gemm_load_stage(A,Bt,As+(cur^1)*AELE,Bs+(cur^1)*BELE,tid,bm,bn,K,lda,conv,kt+1);
      cp_wait<1>();
    } else {
      cp_wait<0>();
    }
    __syncthreads();
    const uint32_t ab = As32 + (uint32_t)(cur*AELE*2);
    const uint32_t bb = Bs32 + (uint32_t)(cur*BELE*2);
    #pragma unroll
    for (int ks=0; ks<2; ks++){
      const uint32_t kbB = (uint32_t)(ks*32);   // 16 halves = 32 bytes
      uint32_t af[2][4], bf[8][2];
      LDSM4(af[0][0], af[0][1], af[0][2], af[0][3], ab + aoffm[0] + kbB);
      LDSM4(af[1][0], af[1][1], af[1][2], af[1][3], ab + aoffm[1] + kbB);
      #pragma unroll
      for (int p=0; p<4; p++)
        LDSM4(bf[2*p][0], bf[2*p][1], bf[2*p+1][0], bf[2*p+1][1], bb + boffp[p] + kbB);
      #pragma unroll
      for (int mt=0; mt<2; mt++)
        #pragma unroll
        for (int nt=0; nt<8; nt++)
          mma16(acc[mt][nt], af[mt], bf[nt]);
    }
    __syncthreads();
  }

  float* Cf = (float*)Cp;
  __half* Ch = (__half*)Cp;
  #pragma unroll
  for (int mt=0; mt<2; mt++){
    const int r0 = bm + rowW + mt*16 + (lane>>2);
    #pragma unroll
    for (int nt=0; nt<8; nt++){
      const int c0 = bn + colW + nt*8 + (lane&3)*2;
      const float bb0 = bias ? bias[c0]   : 0.f;
      const float bb1 = bias ? bias[c0+1] : 0.f;
      #pragma unroll
      for (int rr=0; rr<2; rr++){
        const int r = r0 + rr*8;
        float v0 = acc[mt][nt][rr*2+0] + bb0;
        float v1 = acc[mt][nt][rr*2+1] + bb1;
        if (act==1){ v0 = gelu_f(v0); v1 = gelu_f(v1); }
        else if (act==2){ v0 = silu_f(v0); v1 = silu_f(v1); }
        if (Rres){
          const float* rp = Rres + (size_t)r*N + c0;
          v0 += rp[0]; v1 += rp[1];
        }
        if (ohalf){
          __half2 h = __floats2half2_rn(v0, v1);
          *(__half2*)(Ch + (size_t)r*N + c0) = h;
        } else {
          *(float2*)(Cf + (size_t)r*N + c0) = make_float2(v0, v1);
        }
      }
    }
  }
}

// ------------------------- channel attention -------------------------------
__global__ __launch_bounds__(256) void attn_kernel(
    const float* __restrict__ q, const float* __restrict__ k,
    const float* __restrict__ v, const float* __restrict__ temp,
    const float* __restrict__ x, float* __restrict__ y)
{
  __shared__ float Qs[64*36];
  __shared__ float Ks[64*36];
  __shared__ float Ps[64*65];
  const int bh = blockIdx.x;
  const int b = bh >> 4, h = bh & 15;
  const size_t base = (size_t)b*TDSZ + (size_t)h*(64*TSEQ);
  const float* Q  = q + base;
  const float* Kp = k + base;
  const float* V  = v + base;
  const int tid = threadIdx.x;
  const int tx = tid & 15, ty = tid >> 4;
  const int r0 = ty*4, c0 = tx*4;

  float acc[16];
  #pragma unroll
  for (int i2=0;i2<16;i2++) acc[i2]=0.f;

  for (int t0 = 0; t0 < TSEQ; t0 += 32){
    #pragma unroll
    for (int j=0;j<2;j++){
      int i = tid + j*256;
      int row = i >> 3, col = (i & 7)*4;
      *(float4*)(Qs + row*36 + col) = *(const float4*)(Q  + row*TSEQ + t0 + col);
      *(float4*)(Ks + row*36 + col) = *(const float4*)(Kp + row*TSEQ + t0 + col);
    }
    __syncthreads();
    for (int kk=0; kk<32; kk++){
      float qv[4], kv[4];
      #pragma unroll
      for (int i=0;i<4;i++) qv[i] = Qs[(r0+i)*36 + kk];
      #pragma unroll
      for (int j=0;j<4;j++) kv[j] = Ks[(c0+j)*36 + kk];
      #pragma unroll
      for (int i=0;i<4;i++)
        #pragma unroll
        for (int j=0;j<4;j++) acc[i*4+j] += qv[i]*kv[j];
    }
    __syncthreads();
  }
  const float tmp = temp[h];
  #pragma unroll
  for (int i=0;i<4;i++)
    #pragma unroll
    for (int j=0;j<4;j++) Ps[(r0+i)*65 + c0 + j] = acc[i*4+j]*tmp;
  __syncthreads();

  if (tid < 64){
    float* row = Ps + tid*65;
    float m = row[0];
    for (int e=1;e<64;e++) m = fmaxf(m, row[e]);
    float s = 0.f;
    for (int e=0;e<64;e++){ float ev = expf(row[e]-m); row[e]=ev; s+=ev; }
    float inv = 1.f/s;
    for (int e=0;e<64;e++) row[e] *= inv;
  }
  __syncthreads();

  const int tc = tx*2;
  for (int t0 = 0; t0 < TSEQ; t0 += 32){
    #pragma unroll
    for (int j=0;j<2;j++){
      int i = tid + j*256;
      int row = i >> 3, col = (i & 7)*4;
      *(float4*)(Qs + row*36 + col) = *(const float4*)(V + row*TSEQ + t0 + col);
    }
    __syncthreads();
    float a2[4][2];
    #pragma unroll
    for (int i=0;i<4;i++){ a2[i][0]=0.f; a2[i][1]=0.f; }
    for (int e=0;e<64;e++){
      float v0 = Qs[e*36 + tc], v1 = Qs[e*36 + tc + 1];
      #pragma unroll
      for (int i=0;i<4;i++){
        float p = Ps[(r0+i)*65 + e];
        a2[i][0] += p*v0; a2[i][1] += p*v1;
      }
    }
    #pragma unroll
    for (int i=0;i<4;i++){
      size_t o = base + (size_t)(r0+i)*TSEQ + t0 + tc;
      y[o]   = a2[i][0] + x[o];
      y[o+1] = a2[i][1] + x[o+1];
    }
    __syncthreads();
  }
}

// ------------------------- launch ------------------------------------------
static void launch_gemm(const __half* A, const __half* Bt, const float* bias,
                        const float* R, void* C, int M, int N, int K,
                        int act, int conv, int ohalf){
  dim3 grid(N/BN, M/BM);
  gemm_kernel<<<grid, 256>>>(A, Bt, bias, R, C, M, N, K, act, conv, ohalf);
}
static void launch_tcopy(const float* src, __half* dst, int R, int C){
  dim3 grid(C/32, R/32), block(32,8);
  tcopy_kernel<<<grid, block>>>(src, dst, R, C);
}

extern "C" void kernel_launch(void* const* d_in, const int* in_sizes, int n_in,
                              void* d_out, int out_size) {
  const float* x       = (const float*)d_in[0];
  const float* q_w     = (const float*)d_in[1];
  const float* q_b     = (const float*)d_in[2];
  const float* k_w     = (const float*)d_in[3];
  const float* k_b     = (const float*)d_in[4];
  const float* v_w     = (const float*)d_in[5];
  const float* v_b     = (const float*)d_in[6];
  const float* temp    = (const float*)d_in[7];
  const float* ln1_w   = (const float*)d_in[8];
  const float* ln1_b   = (const float*)d_in[9];
  const float* ln2_w   = (const float*)d_in[10];
  const float* ln2_b   = (const float*)d_in[11];
  const float* ln3_w   = (const float*)d_in[12];
  const float* ln3_b   = (const float*)d_in[13];
  const float* ln4_w   = (const float*)d_in[14];
  const float* ln4_b   = (const float*)d_in[15];
  const float* lin1_w  = (const float*)d_in[16];
  const float* lin1_b  = (const float*)d_in[17];
  const float* lin2_w  = (const float*)d_in[18];
  const float* lin2_b  = (const float*)d_in[19];
  const float* mlp1_w1 = (const float*)d_in[20];
  const float* mlp1_b1 = (const float*)d_in[21];
  const float* mlp1_w2 = (const float*)d_in[22];
  const float* mlp1_b2 = (const float*)d_in[23];
  const float* mlp2_w1 = (const float*)d_in[24];
  const float* mlp2_b1 = (const float*)d_in[25];
  const float* mlp2_w2 = (const float*)d_in[26];
  const float* mlp2_b2 = (const float*)d_in[27];
  const float* conv1_w = (const float*)d_in[28];
  const float* conv1_b = (const float*)d_in[29];
  const float* conv2_w = (const float*)d_in[30];
  const float* conv2_b = (const float*)d_in[31];
  float* out = (float*)d_out;

  __half *p_ln, *p_wide, *p_dy, *p_c1;
  float  *p_q, *p_k, *p_v, *p_y, *p_y2, *p_b2f;
  __half *p_MT, *p_MinvA, *p_W1fT, *p_W2fT, *p_Bc1t, *p_Bc2t;
  __half *p_qwt, *p_kwt, *p_vwt, *p_lin1t, *p_lin2r, *p_m11t, *p_m12t, *p_m21t, *p_m22t;
  cudaGetSymbolAddress((void**)&p_ln,   g_ln);
  cudaGetSymbolAddress((void**)&p_wide, g_wide);
  cudaGetSymbolAddress((void**)&p_dy,   g_dy);
  cudaGetSymbolAddress((void**)&p_c1,   g_c1);
  cudaGetSymbolAddress((void**)&p_q,    g_q);
  cudaGetSymbolAddress((void**)&p_k,    g_k);
  cudaGetSymbolAddress((void**)&p_v,    g_v);
  cudaGetSymbolAddress((void**)&p_y,    g_y);
  cudaGetSymbolAddress((void**)&p_y2,   g_y2);
  cudaGetSymbolAddress((void**)&p_b2f,  g_b2f);
  cudaGetSymbolAddress((void**)&p_MT,   g_MT);
  cudaGetSymbolAddress((void**)&p_MinvA,g_MinvA);
  cudaGetSymbolAddress((void**)&p_W1fT, g_W1fT);
  cudaGetSymbolAddress((void**)&p_W2fT, g_W2fT);
  cudaGetSymbolAddress((void**)&p_Bc1t, g_Bc1t);
  cudaGetSymbolAddress((void**)&p_Bc2t, g_Bc2t);
  cudaGetSymbolAddress((void**)&p_qwt,  g_qwt);
  cudaGetSymbolAddress((void**)&p_kwt,  g_kwt);
  cudaGetSymbolAddress((void**)&p_vwt,  g_vwt);
  cudaGetSymbolAddress((void**)&p_lin1t,g_lin1t);
  cudaGetSymbolAddress((void**)&p_lin2r,g_lin2r);
  cudaGetSymbolAddress((void**)&p_m11t, g_m11t);
  cudaGetSymbolAddress((void**)&p_m12t, g_m12t);
  cudaGetSymbolAddress((void**)&p_m21t, g_m21t);
  cudaGetSymbolAddress((void**)&p_m22t, g_m22t);

  // attention block; launch index 3 = Q-projection GEMM (profiling target)
  ln_kernel<<<TOK, 256>>>(x, ln1_w, ln1_b, p_ln);                               // 0
  launch_tcopy(q_w, p_qwt, DMODEL, DMODEL);                                     // 1
  launch_tcopy(k_w, p_kwt, DMODEL, DMODEL);                                     // 2
  launch_gemm(p_ln, p_qwt, q_b, nullptr, p_q, TOK, DMODEL, DMODEL, 0, 0, 0);    // 3
  launch_tcopy(v_w, p_vwt, DMODEL, DMODEL);                                     // 4
  launch_gemm(p_ln, p_kwt, k_b, nullptr, p_k, TOK, DMODEL, DMODEL, 0, 0, 0);
  launch_gemm(p_ln, p_vwt, v_b, nullptr, p_v, TOK, DMODEL, DMODEL, 0, 0, 0);
  attn_kernel<<<512, 256>>>(p_q, p_k, p_v, temp, x, p_y);

  // prep: DCT folds + weight transposes + conv packs
  build_dct_kernel<<<4096, 256>>>();
  launch_tcopy(lin1_w, p_lin1t, DMODEL, DFF);
  rcopy_kernel<<<(DFF*DMODEL)/1024, 256>>>(lin2_w, p_lin2r);
  launch_tcopy(mlp1_w1, p_m11t, DMODEL, DFF);
  launch_tcopy(mlp1_w2, p_m12t, DFF, DMODEL);
  launch_tcopy(mlp2_w1, p_m21t, DMODEL, DFF);
  launch_tcopy(mlp2_w2, p_m22t, DFF, DMODEL);
  pack_conv_kernel<<<12288, 256>>>(conv1_w, p_Bc1t);
  pack_conv_kernel<<<12288, 256>>>(conv2_w, p_Bc2t);
  launch_gemm(p_lin1t, p_MT,    nullptr, nullptr, p_W1fT, DFF,    DMODEL, DMODEL, 0, 0, 1);
  launch_gemm(p_MinvA, p_lin2r, nullptr, nullptr, p_W2fT, DMODEL, DFF,    DMODEL, 0, 0, 1);
  fold_bias_kernel<<<DMODEL, 256>>>(lin2_b);

  // DCT-folded MLP
  ln_kernel<<<TOK, 256>>>(p_y, ln2_w, ln2_b, p_ln);
  launch_gemm(p_ln,   p_W1fT, lin1_b, nullptr, p_wide, TOK, DFF,    DMODEL, 1, 0, 1);
  launch_gemm(p_wide, p_W2fT, p_b2f,  nullptr, p_dy,   TOK, DMODEL, DFF,    0, 0, 1);

  // mlp1(d_y) + y
  launch_gemm(p_dy,   p_m11t, mlp1_b1, nullptr, p_wide, TOK, DFF,    DMODEL, 1, 0, 1);
  launch_gemm(p_wide, p_m12t, mlp1_b2, p_y,     p_y2,   TOK, DMODEL, DFF,    0, 0, 0);

  // mlp2(ln3(y)) added
  ln_kernel<<<TOK, 256>>>(p_y, ln3_w, ln3_b, p_ln);
  launch_gemm(p_ln,   p_m21t, mlp2_b1, nullptr, p_wide, TOK, DFF,    DMODEL, 1, 0, 1);
  launch_gemm(p_wide, p_m22t, mlp2_b2, p_y2,    p_y2,   TOK, DMODEL, DFF,    0, 0, 0);

  // conv path (shifted GEMMs, K=3072), silu between; final residual y2
  ln_kernel<<<TOK, 256>>>(p_y2, ln4_w, ln4_b, p_ln);
  launch_gemm(p_ln, p_Bc1t, conv1_b, nullptr, p_c1, TOK, DMODEL, 3*DMODEL, 2, 1, 1);
  launch_gemm(p_c1, p_Bc2t, conv2_b, p_y2,    out,  TOK, DMODEL, 3*DMODEL, 0, 1, 0);
}

// round 10
// speedup vs baseline: 1.8670x; 1.0153x over previous
#include <cuda_runtime.h>
#include <cuda_fp16.h>
#include <math.h>
#include <stdint.h>

#define TOK    16384
#define DMODEL 1024
#define DFF    2048
#define TSEQ   512
#define TDSZ   (TSEQ*DMODEL)

// ------------------------- scratch (device globals; no allocs) -------------
__device__ __half g_ln  [TOK*DMODEL];
__device__ __half g_wide[TOK*DFF];
__device__ __half g_dy  [TOK*DMODEL];
__device__ __half g_c1  [TOK*DMODEL];
__device__ float  g_q   [TOK*DMODEL];
__device__ float  g_k   [TOK*DMODEL];
__device__ float  g_v   [TOK*DMODEL];
__device__ float  g_y   [TOK*DMODEL];
__device__ float  g_y2  [TOK*DMODEL];
__device__ __half g_MT   [DMODEL*DMODEL];
__device__ __half g_MinvA[DMODEL*DMODEL];
__device__ __half g_W1fT [DFF*DMODEL];
__device__ __half g_W2fT [DMODEL*DFF];
__device__ float  g_b2f  [DMODEL];
__device__ __half g_Bc1t [DMODEL*3*DMODEL];
__device__ __half g_Bc2t [DMODEL*3*DMODEL];
__device__ __half g_qwt  [DMODEL*DMODEL];
__device__ __half g_kwt  [DMODEL*DMODEL];
__device__ __half g_vwt  [DMODEL*DMODEL];
__device__ __half g_lin1t[DFF*DMODEL];
__device__ __half g_lin2r[DFF*DMODEL];
__device__ __half g_m11t [DFF*DMODEL];
__device__ __half g_m12t [DMODEL*DFF];
__device__ __half g_m21t [DFF*DMODEL];
__device__ __half g_m22t [DMODEL*DFF];

// ------------------------- helpers ----------------------------------------
__device__ __forceinline__ void mma16(float* d, const uint32_t* a, const uint32_t* b){
  asm volatile(
    "mma.sync.aligned.m16n8k16.row.col.f32.f16.f16.f32 "
    "{%0,%1,%2,%3}, {%4,%5,%6,%7}, {%8,%9}, {%0,%1,%2,%3};"
    : "+f"(d[0]), "+f"(d[1]), "+f"(d[2]), "+f"(d[3])
    : "r"(a[0]), "r"(a[1]), "r"(a[2]), "r"(a[3]), "r"(b[0]), "r"(b[1]));
}
#define LDSM4(r0,r1,r2,r3,addr) \
  asm volatile("ldmatrix.sync.aligned.m8n8.x4.shared.b16 {%0,%1,%2,%3}, [%4];" \
               : "=r"(r0), "=r"(r1), "=r"(r2), "=r"(r3) : "r"(addr))
__device__ __forceinline__ void cp16(void* sdst, const void* gsrc, bool pred){
  uint32_t s = (uint32_t)__cvta_generic_to_shared(sdst);
  int n = pred ? 16 : 0;
  asm volatile("cp.async.cg.shared.global [%0], [%1], 16, %2;" :: "r"(s), "l"(gsrc), "r"(n));
}
__device__ __forceinline__ void cp_commit(){ asm volatile("cp.async.commit_group;"); }
template<int N> __device__ __forceinline__ void cp_wait(){
  asm volatile("cp.async.wait_group %0;" :: "n"(N));
}
__device__ __forceinline__ float gelu_f(float x){
  return 0.5f*x*(1.f + erff(x*0.70710678118654752f));
}
__device__ __forceinline__ float silu_f(float x){ return x/(1.f+expf(-x)); }

// ------------------------- prep kernels ------------------------------------
__global__ void build_dct_kernel(){
  int idx = blockIdx.x*256 + threadIdx.x;
  int i = idx >> 10, j = idx & 1023;        // i = n, j = k
  const float c = 3.14159265358979323846f/2048.f;
  int m1 = ((2*i+1)*j) & 4095;
  g_MT[idx] = __float2half(2.f*cosf((float)m1 * c));
  float sc = (j==0) ? (0.5f/1024.f) : (1.f/1024.f);
  g_MinvA[idx] = __float2half(cosf((float)m1 * c) * sc);
}

__global__ void pack_conv_kernel(const float* __restrict__ w, __half* __restrict__ Bt){
  int idx = blockIdx.x*256 + threadIdx.x;
  int o = idx / 3072;
  int rem = idx - o*3072;
  int r = rem >> 10;
  int i = rem & 1023;
  Bt[idx] = __float2half(w[((o<<10) + i)*3 + r]);
}

__global__ void tcopy_kernel(const float* __restrict__ src, __half* __restrict__ dst,
                             int R, int C){
  __shared__ float t[32][33];
  int bx = blockIdx.x*32, by = blockIdx.y*32;
  int x = threadIdx.x, y = threadIdx.y;
  #pragma unroll
  for (int j=0;j<32;j+=8)
    t[y+j][x] = src[(size_t)(by+y+j)*C + bx + x];
  __syncthreads();
  #pragma unroll
  for (int j=0;j<32;j+=8)
    dst[(size_t)(bx+y+j)*R + by + x] = __float2half(t[x][y+j]);
}

__global__ void rcopy_kernel(const float* __restrict__ src, __half* __restrict__ dst){
  int idx = blockIdx.x*256 + threadIdx.x;
  float4 v = *(const float4*)(src + idx*4);
  __half2 h0 = __floats2half2_rn(v.x, v.y);
  __half2 h1 = __floats2half2_rn(v.z, v.w);
  *(uint2*)(dst + idx*4) = make_uint2(*(uint32_t*)&h0, *(uint32_t*)&h1);
}

__global__ __launch_bounds__(256) void fold_bias_kernel(const float* __restrict__ b2){
  __shared__ float red[8];
  const int n = blockIdx.x, tid = threadIdx.x;
  const int lane = tid & 31, warp = tid >> 5;
  float s = 0.f;
  for (int k = tid; k < 1024; k += 256) s += b2[k]*__half2float(g_MinvA[(n<<10)+k]);
  #pragma unroll
  for (int o=16;o;o>>=1) s += __shfl_xor_sync(0xffffffffu,s,o);
  if (lane==0) red[warp]=s;
  __syncthreads();
  if (tid==0){
    float t=0.f;
    #pragma unroll
    for (int w2=0;w2<8;w2++) t+=red[w2];
    g_b2f[n]=t;
  }
}

// ------------------------- LayerNorm (f16 out) ------------------------------
__global__ __launch_bounds__(256) void ln_kernel(
    const float* __restrict__ x, const float* __restrict__ gw,
    const float* __restrict__ gb, __half* __restrict__ out)
{
  __shared__ float rs[8], rq[8], mv[2];
  const int row = blockIdx.x, tid = threadIdx.x;
  const int lane = tid & 31, warp = tid >> 5;
  const float4 xv = *(const float4*)(x + (size_t)row*1024 + tid*4);
  float s = xv.x+xv.y+xv.z+xv.w;
  float q = xv.x*xv.x+xv.y*xv.y+xv.z*xv.z+xv.w*xv.w;
  #pragma unroll
  for (int o=16;o;o>>=1){ s += __shfl_xor_sync(0xffffffffu,s,o); q += __shfl_xor_sync(0xffffffffu,q,o); }
  if (lane==0){ rs[warp]=s; rq[warp]=q; }
  __syncthreads();
  if (tid==0){
    float ss=0.f, qq=0.f;
    #pragma unroll
    for (int w2=0;w2<8;w2++){ ss+=rs[w2]; qq+=rq[w2]; }
    float m = ss*(1.f/1024.f);
    float var = qq*(1.f/1024.f) - m*m;
    mv[0]=m; mv[1]=rsqrtf(var + 1e-5f);
  }
  __syncthreads();
  const float m = mv[0], inv = mv[1];
  const float4 g4 = *(const float4*)(gw + tid*4);
  const float4 b4 = *(const float4*)(gb + tid*4);
  __half2 h0 = __floats2half2_rn((xv.x-m)*inv*g4.x + b4.x, (xv.y-m)*inv*g4.y + b4.y);
  __half2 h1 = __floats2half2_rn((xv.z-m)*inv*g4.z + b4.z, (xv.w-m)*inv*g4.w + b4.w);
  *(uint2*)(out + (size_t)row*1024 + tid*4) = make_uint2(*(uint32_t*)&h0, *(uint32_t*)&h1);
}

// ------------------------- fp16 GEMM: 4-stage cp.async ring -----------------
#define BM 128
#define BN 128
#define BK 32
#define STAGES 4
#define ASTRH 40
#define BTSTRH 40
#define AELE (BM*ASTRH)
#define BELE (BN*BTSTRH)
#define GEMM_SMEM_BYTES (STAGES*(AELE+BELE)*2)

__device__ __forceinline__ void gemm_load_stage(
    const __half* __restrict__ A, const __half* __restrict__ Bt,
    __half* asb, __half* bsb, int tid, int bm, int bn, int K, int lda,
    int conv, int kt)
{
  const int k0 = kt*BK;
  int roff = 0, kk0 = k0;
  if (conv){ roff = (k0 >> 10) - 1; kk0 = k0 & 1023; }
  #pragma unroll
  for (int j=0;j<2;j++){
    int i = tid + j*256;
    int ar = i >> 2, ac = (i & 3)*8;
    int grow = bm + ar;
    bool pr = true; int srow = grow;
    if (conv){
      int tt = grow & (TSEQ-1);
      int tp = tt + roff;
      pr = (tp >= 0) && (tp < TSEQ);
      srow = pr ? (grow + roff) : grow;
    }
    cp16(asb + ar*ASTRH + ac, A + (size_t)srow*lda + kk0 + ac, pr);
  }
  #pragma unroll
  for (int j=0;j<2;j++){
    int i = tid + j*256;
    int br = i >> 2, bc = (i & 3)*8;
    cp16(bsb + br*BTSTRH + bc, Bt + (size_t)(bn+br)*K + k0 + bc, true);
  }
  cp_commit();
}

__global__ __launch_bounds__(256) void gemm_kernel(
    const __half* __restrict__ A, const __half* __restrict__ Bt,
    const float* __restrict__ bias, const float* __restrict__ Rres,
    void* __restrict__ Cp, int M, int N, int K, int act, int conv, int ohalf)
{
  extern __shared__ __align__(16) __half sm[];
  __half* As = sm;                       // STAGES * AELE
  __half* Bs = sm + STAGES*AELE;         // STAGES * BELE
  const int tid = threadIdx.x;
  const int bm = blockIdx.y*BM, bn = blockIdx.x*BN;
  const int lane = tid & 31, warp = tid >> 5;
  const int wm = warp >> 1, wn = warp & 1;
  const int rowW = wm*32, colW = wn*64;
  const int lda = conv ? DMODEL : K;
  const int KT = K / BK;

  const uint32_t As32 = (uint32_t)__cvta_generic_to_shared(As);
  const uint32_t Bs32 = (uint32_t)__cvta_generic_to_shared(Bs);
  uint32_t aoffm[2];
  #pragma unroll
  for (int mt=0; mt<2; mt++)
    aoffm[mt] = (uint32_t)(((rowW + mt*16 + (lane & 15))*ASTRH + ((lane >> 4)*8))*2);
  uint32_t boffp[4];
  #pragma unroll
  for (int p=0; p<4; p++)
    boffp[p] = (uint32_t)(((colW + p*16 + (lane & 7) + ((lane >> 4)*8))*BTSTRH
                          + (((lane >> 3) & 1)*8))*2);

  float acc[2][8][4];
  #pragma unroll
  for (int a1=0;a1<2;a1++)
    #pragma unroll
    for (int a2=0;a2<8;a2++)
      #pragma unroll
      for (int a3=0;a3<4;a3++) acc[a1][a2][a3]=0.f;

  // prologue: STAGES-1 stages in flight
  #pragma unroll
  for (int s=0; s<STAGES-1; s++){
    if (s < KT)
      gemm_load_stage(A,Bt,As+s*AELE,Bs+s*BELE,tid,bm,bn,K,lda,conv,s);
    else
      cp_commit();
  }

  for (int kt=0; kt<KT; kt++){
    const int cur = kt & (STAGES-1);
    cp_wait<STAGES-2>();        // stage kt has arrived (this thread's part)
    __syncthreads();            // publish all threads' parts; all warps done with slot (kt-1)
    const int nxt = kt + STAGES - 1;
    if (nxt < KT)
      gemm_load_stage(A,Bt,As+(nxt&(STAGES-1))*AELE,Bs+(nxt&(STAGES-1))*BELE,
                      tid,bm,bn,K,lda,conv,nxt);
    else
      cp_commit();

    const uint32_t ab = As32 + (uint32_t)(cur*AELE*2);
    const uint32_t bb = Bs32 + (uint32_t)(cur*BELE*2);
    #pragma unroll
    for (int ks=0; ks<2; ks++){
      const uint32_t kbB = (uint32_t)(ks*32);
      uint32_t af[2][4], bf[8][2];
      LDSM4(af[0][0], af[0][1], af[0][2], af[0][3], ab + aoffm[0] + kbB);
      LDSM4(af[1][0], af[1][1], af[1][2], af[1][3], ab + aoffm[1] + kbB);
      #pragma unroll
      for (int p=0; p<4; p++)
        LDSM4(bf[2*p][0], bf[2*p][1], bf[2*p+1][0], bf[2*p+1][1], bb + boffp[p] + kbB);
      #pragma unroll
      for (int mt=0; mt<2; mt++)
        #pragma unroll
        for (int nt=0; nt<8; nt++)
          mma16(acc[mt][nt], af[mt], bf[nt]);
    }
  }

  float* Cf = (float*)Cp;
  __half* Ch = (__half*)Cp;
  #pragma unroll
  for (int mt=0; mt<2; mt++){
    const int r0 = bm + rowW + mt*16 + (lane>>2);
    #pragma unroll
    for (int nt=0; nt<8; nt++){
      const int c0 = bn + colW + nt*8 + (lane&3)*2;
      const float bb0 = bias ? bias[c0]   : 0.f;
      const float bb1 = bias ? bias[c0+1] : 0.f;
      #pragma unroll
      for (int rr=0; rr<2; rr++){
        const int r = r0 + rr*8;
        float v0 = acc[mt][nt][rr*2+0] + bb0;
        float v1 = acc[mt][nt][rr*2+1] + bb1;
        if (act==1){ v0 = gelu_f(v0); v1 = gelu_f(v1); }
        else if (act==2){ v0 = silu_f(v0); v1 = silu_f(v1); }
        if (Rres){
          const float* rp = Rres + (size_t)r*N + c0;
          v0 += rp[0]; v1 += rp[1];
        }
        if (ohalf){
          __half2 h = __floats2half2_rn(v0, v1);
          *(__half2*)(Ch + (size_t)r*N + c0) = h;
        } else {
          *(float2*)(Cf + (size_t)r*N + c0) = make_float2(v0, v1);
        }
      }
    }
  }
}

// ------------------------- channel attention -------------------------------
__global__ __launch_bounds__(256) void attn_kernel(
    const float* __restrict__ q, const float* __restrict__ k,
    const float* __restrict__ v, const float* __restrict__ temp,
    const float* __restrict__ x, float* __restrict__ y)
{
  __shared__ float Qs[64*36];
  __shared__ float Ks[64*36];
  __shared__ float Ps[64*65];
  const int bh = blockIdx.x;
  const int b = bh >> 4, h = bh & 15;
  const size_t base = (size_t)b*TDSZ + (size_t)h*(64*TSEQ);
  const float* Q  = q + base;
  const float* Kp = k + base;
  const float* V  = v + base;
  const int tid = threadIdx.x;
  const int tx = tid & 15, ty = tid >> 4;
  const int r0 = ty*4, c0 = tx*4;

  float acc[16];
  #pragma unroll
  for (int i2=0;i2<16;i2++) acc[i2]=0.f;

  for (int t0 = 0; t0 < TSEQ; t0 += 32){
    #pragma unroll
    for (int j=0;j<2;j++){
      int i = tid + j*256;
      int row = i >> 3, col = (i & 7)*4;
      *(float4*)(Qs + row*36 + col) = *(const float4*)(Q  + row*TSEQ + t0 + col);
      *(float4*)(Ks + row*36 + col) = *(const float4*)(Kp + row*TSEQ + t0 + col);
    }
    __syncthreads();
    for (int kk=0; kk<32; kk++){
      float qv[4], kv[4];
      #pragma unroll
      for (int i=0;i<4;i++) qv[i] = Qs[(r0+i)*36 + kk];
      #pragma unroll
      for (int j=0;j<4;j++) kv[j] = Ks[(c0+j)*36 + kk];
      #pragma unroll
      for (int i=0;i<4;i++)
        #pragma unroll
        for (int j=0;j<4;j++) acc[i*4+j] += qv[i]*kv[j];
    }
    __syncthreads();
  }
  const float tmp = temp[h];
  #pragma unroll
  for (int i=0;i<4;i++)
    #pragma unroll
    for (int j=0;j<4;j++) Ps[(r0+i)*65 + c0 + j] = acc[i*4+j]*tmp;
  __syncthreads();

  if (tid < 64){
    float* row = Ps + tid*65;
    float m = row[0];
    for (int e=1;e<64;e++) m = fmaxf(m, row[e]);
    float s = 0.f;
    for (int e=0;e<64;e++){ float ev = expf(row[e]-m); row[e]=ev; s+=ev; }
    float inv = 1.f/s;
    for (int e=0;e<64;e++) row[e] *= inv;
  }
  __syncthreads();

  const int tc = tx*2;
  for (int t0 = 0; t0 < TSEQ; t0 += 32){
    #pragma unroll
    for (int j=0;j<2;j++){
      int i = tid + j*256;
      int row = i >> 3, col = (i & 7)*4;
      *(float4*)(Qs + row*36 + col) = *(const float4*)(V + row*TSEQ + t0 + col);
    }
    __syncthreads();
    float a2[4][2];
    #pragma unroll
    for (int i=0;i<4;i++){ a2[i][0]=0.f; a2[i][1]=0.f; }
    for (int e=0;e<64;e++){
      float v0 = Qs[e*36 + tc], v1 = Qs[e*36 + tc + 1];
      #pragma unroll
      for (int i=0;i<4;i++){
        float p = Ps[(r0+i)*65 + e];
        a2[i][0] += p*v0; a2[i][1] += p*v1;
      }
    }
    #pragma unroll
    for (int i=0;i<4;i++){
      size_t o = base + (size_t)(r0+i)*TSEQ + t0 + tc;
      y[o]   = a2[i][0] + x[o];
      y[o+1] = a2[i][1] + x[o+1];
    }
    __syncthreads();
  }
}

// ------------------------- launch ------------------------------------------
static void launch_gemm(const __half* A, const __half* Bt, const float* bias,
                        const float* R, void* C, int M, int N, int K,
                        int act, int conv, int ohalf){
  dim3 grid(N/BN, M/BM);
  gemm_kernel<<<grid, 256, GEMM_SMEM_BYTES>>>(A, Bt, bias, R, C, M, N, K, act, conv, ohalf);
}
static void launch_tcopy(const float* src, __half* dst, int R, int C){
  dim3 grid(C/32, R/32), block(32,8);
  tcopy_kernel<<<grid, block>>>(src, dst, R, C);
}

extern "C" void kernel_launch(void* const* d_in, const int* in_sizes, int n_in,
                              void* d_out, int out_size) {
  const float* x       = (const float*)d_in[0];
  const float* q_w     = (const float*)d_in[1];
  const float* q_b     = (const float*)d_in[2];
  const float* k_w     = (const float*)d_in[3];
  const float* k_b     = (const float*)d_in[4];
  const float* v_w     = (const float*)d_in[5];
  const float* v_b     = (const float*)d_in[6];
  const float* temp    = (const float*)d_in[7];
  const float* ln1_w   = (const float*)d_in[8];
  const float* ln1_b   = (const float*)d_in[9];
  const float* ln2_w   = (const float*)d_in[10];
  const float* ln2_b   = (const float*)d_in[11];
  const float* ln3_w   = (const float*)d_in[12];
  const float* ln3_b   = (const float*)d_in[13];
  const float* ln4_w   = (const float*)d_in[14];
  const float* ln4_b   = (const float*)d_in[15];
  const float* lin1_w  = (const float*)d_in[16];
  const float* lin1_b  = (const float*)d_in[17];
  const float* lin2_w  = (const float*)d_in[18];
  const float* lin2_b  = (const float*)d_in[19];
  const float* mlp1_w1 = (const float*)d_in[20];
  const float* mlp1_b1 = (const float*)d_in[21];
  const float* mlp1_w2 = (const float*)d_in[22];
  const float* mlp1_b2 = (const float*)d_in[23];
  const float* mlp2_w1 = (const float*)d_in[24];
  const float* mlp2_b1 = (const float*)d_in[25];
  const float* mlp2_w2 = (const float*)d_in[26];
  const float* mlp2_b2 = (const float*)d_in[27];
  const float* conv1_w = (const float*)d_in[28];
  const float* conv1_b = (const float*)d_in[29];
  const float* conv2_w = (const float*)d_in[30];
  const float* conv2_b = (const float*)d_in[31];
  float* out = (float*)d_out;

  cudaFuncSetAttribute(gemm_kernel, cudaFuncAttributeMaxDynamicSharedMemorySize, GEMM_SMEM_BYTES);

  __half *p_ln, *p_wide, *p_dy, *p_c1;
  float  *p_q, *p_k, *p_v, *p_y, *p_y2, *p_b2f;
  __half *p_MT, *p_MinvA, *p_W1fT, *p_W2fT, *p_Bc1t, *p_Bc2t;
  __half *p_qwt, *p_kwt, *p_vwt, *p_lin1t, *p_lin2r, *p_m11t, *p_m12t, *p_m21t, *p_m22t;
  cudaGetSymbolAddress((void**)&p_ln,   g_ln);
  cudaGetSymbolAddress((void**)&p_wide, g_wide);
  cudaGetSymbolAddress((void**)&p_dy,   g_dy);
  cudaGetSymbolAddress((void**)&p_c1,   g_c1);
  cudaGetSymbolAddress((void**)&p_q,    g_q);
  cudaGetSymbolAddress((void**)&p_k,    g_k);
  cudaGetSymbolAddress((void**)&p_v,    g_v);
  cudaGetSymbolAddress((void**)&p_y,    g_y);
  cudaGetSymbolAddress((void**)&p_y2,   g_y2);
  cudaGetSymbolAddress((void**)&p_b2f,  g_b2f);
  cudaGetSymbolAddress((void**)&p_MT,   g_MT);
  cudaGetSymbolAddress((void**)&p_MinvA,g_MinvA);
  cudaGetSymbolAddress((void**)&p_W1fT, g_W1fT);
  cudaGetSymbolAddress((void**)&p_W2fT, g_W2fT);
  cudaGetSymbolAddress((void**)&p_Bc1t, g_Bc1t);
  cudaGetSymbolAddress((void**)&p_Bc2t, g_Bc2t);
  cudaGetSymbolAddress((void**)&p_qwt,  g_qwt);
  cudaGetSymbolAddress((void**)&p_kwt,  g_kwt);
  cudaGetSymbolAddress((void**)&p_vwt,  g_vwt);
  cudaGetSymbolAddress((void**)&p_lin1t,g_lin1t);
  cudaGetSymbolAddress((void**)&p_lin2r,g_lin2r);
  cudaGetSymbolAddress((void**)&p_m11t, g_m11t);
  cudaGetSymbolAddress((void**)&p_m12t, g_m12t);
  cudaGetSymbolAddress((void**)&p_m21t, g_m21t);
  cudaGetSymbolAddress((void**)&p_m22t, g_m22t);

  // attention block; launch index 3 = Q-projection GEMM (profiling target)
  ln_kernel<<<TOK, 256>>>(x, ln1_w, ln1_b, p_ln);                               // 0
  launch_tcopy(q_w, p_qwt, DMODEL, DMODEL);                                     // 1
  launch_tcopy(k_w, p_kwt, DMODEL, DMODEL);                                     // 2
  launch_gemm(p_ln, p_qwt, q_b, nullptr, p_q, TOK, DMODEL, DMODEL, 0, 0, 0);    // 3
  launch_tcopy(v_w, p_vwt, DMODEL, DMODEL);                                     // 4
  launch_gemm(p_ln, p_kwt, k_b, nullptr, p_k, TOK, DMODEL, DMODEL, 0, 0, 0);
  launch_gemm(p_ln, p_vwt, v_b, nullptr, p_v, TOK, DMODEL, DMODEL, 0, 0, 0);
  attn_kernel<<<512, 256>>>(p_q, p_k, p_v, temp, x, p_y);

  // prep: DCT folds + weight transposes + conv packs
  build_dct_kernel<<<4096, 256>>>();
  launch_tcopy(lin1_w, p_lin1t, DMODEL, DFF);
  rcopy_kernel<<<(DFF*DMODEL)/1024, 256>>>(lin2_w, p_lin2r);
  launch_tcopy(mlp1_w1, p_m11t, DMODEL, DFF);
  launch_tcopy(mlp1_w2, p_m12t, DFF, DMODEL);
  launch_tcopy(mlp2_w1, p_m21t, DMODEL, DFF);
  launch_tcopy(mlp2_w2, p_m22t, DFF, DMODEL);
  pack_conv_kernel<<<12288, 256>>>(conv1_w, p_Bc1t);
  pack_conv_kernel<<<12288, 256>>>(conv2_w, p_Bc2t);
  launch_gemm(p_lin1t, p_MT,    nullptr, nullptr, p_W1fT, DFF,    DMODEL, DMODEL, 0, 0, 1);
  launch_gemm(p_MinvA, p_lin2r, nullptr, nullptr, p_W2fT, DMODEL, DFF,    DMODEL, 0, 0, 1);
  fold_bias_kernel<<<DMODEL, 256>>>(lin2_b);

  // DCT-folded MLP
  ln_kernel<<<TOK, 256>>>(p_y, ln2_w, ln2_b, p_ln);
  launch_gemm(p_ln,   p_W1fT, lin1_b, nullptr, p_wide, TOK, DFF,    DMODEL, 1, 0, 1);
  launch_gemm(p_wide, p_W2fT, p_b2f,  nullptr, p_dy,   TOK, DMODEL, DFF,    0, 0, 1);

  // mlp1(d_y) + y
  launch_gemm(p_dy,   p_m11t, mlp1_b1, nullptr, p_wide, TOK, DFF,    DMODEL, 1, 0, 1);
  launch_gemm(p_wide, p_m12t, mlp1_b2, p_y,     p_y2,   TOK, DMODEL, DFF,    0, 0, 0);

  // mlp2(ln3(y)) added
  ln_kernel<<<TOK, 256>>>(p_y, ln3_w, ln3_b, p_ln);
  launch_gemm(p_ln,   p_m21t, mlp2_b1, nullptr, p_wide, TOK, DFF,    DMODEL, 1, 0, 1);
  launch_gemm(p_wide, p_m22t, mlp2_b2, p_y2,    p_y2,   TOK, DMODEL, DFF,    0, 0, 0);

  // conv path (shifted GEMMs, K=3072), silu between; final residual y2
  ln_kernel<<<TOK, 256>>>(p_y2, ln4_w, ln4_b, p_ln);
  launch_gemm(p_ln, p_Bc1t, conv1_b, nullptr, p_c1, TOK, DMODEL, 3*DMODEL, 2, 1, 1);
  launch_gemm(p_c1, p_Bc2t, conv2_b, p_y2,    out,  TOK, DMODEL, 3*DMODEL, 0, 1, 0);
}